// round 11
// baseline (speedup 1.0000x reference)
#include <cuda_runtime.h>
#include <cuda_fp16.h>
#include <cstdint>

// Problem constants
#define Bn 8
#define Sn 16
#define En 128
#define TOK (Bn*Sn*32*32)      // 131072
#define Pn (Bn*32*32)          // 8192
#define OC 512

// -------- scratch (device globals) --------
__device__ __half g_ccx[(long)TOK*OC];        // 128MB fp16 gate pre-activations
__device__ float g_c[Pn*En];
__device__ __half g_qkvh[(long)TOK*384];
__device__ __half g_xin2[(long)TOK*256];
__device__ __half g_xs2[(long)TOK*256];
__device__ __half g_ao[(long)TOK*256];
__device__ __half g_xp[(long)TOK*128];
__device__ __half g_hp[Pn*128];
__device__ __half g_bx[(long)OC*1152];
__device__ __half g_bh[(long)OC*1152];
__device__ __half g_bproj[128*256];
__device__ __half g_bqkv[384*256];
__device__ __half g_bout[128*256];

// ==================== helpers ====================
__device__ __forceinline__ uint32_t smem_u32(const void* p) {
    uint32_t a;
    asm("{ .reg .u64 t; cvta.to.shared.u64 t, %1; cvt.u32.u64 %0, t; }" : "=r"(a) : "l"(p));
    return a;
}
__device__ __forceinline__ void cp16(uint32_t dst, const void* src, bool pred) {
    asm volatile("cp.async.cg.shared.global [%0], [%1], 16, %2;"
        :: "r"(dst), "l"(src), "r"(pred ? 16u : 0u));
}
#define CP_COMMIT() asm volatile("cp.async.commit_group;" ::: "memory")
#define CP_WAIT3()  asm volatile("cp.async.wait_group 3;" ::: "memory")

__device__ __forceinline__ void ldm_x4(uint32_t* r, uint32_t addr) {
    asm volatile("ldmatrix.sync.aligned.m8n8.x4.shared.b16 {%0,%1,%2,%3}, [%4];"
        : "=r"(r[0]), "=r"(r[1]), "=r"(r[2]), "=r"(r[3]) : "r"(addr));
}
__device__ __forceinline__ void mma16816(float* d, const uint32_t* a, uint32_t b0, uint32_t b1) {
    asm volatile("mma.sync.aligned.m16n8k16.row.col.f32.f16.f16.f32 "
        "{%0,%1,%2,%3}, {%4,%5,%6,%7}, {%8,%9}, {%0,%1,%2,%3};"
        : "+f"(d[0]), "+f"(d[1]), "+f"(d[2]), "+f"(d[3])
        : "r"(a[0]), "r"(a[1]), "r"(a[2]), "r"(a[3]), "r"(b0), "r"(b1));
}
__device__ __forceinline__ void split_h(float x, __half& hi, __half& lo) {
    hi = __float2half(x);
    lo = __float2half(x - __half2float(hi));
}

// -------------------- small kernels --------------------
__global__ void split_in(const float* __restrict__ inp, __half* __restrict__ x2) {
    long idx = (long)blockIdx.x*blockDim.x + threadIdx.x;
    if (idx >= (long)TOK*64) return;
    long row = idx >> 6; int e2 = idx & 63;
    float2 v = ((const float2*)inp)[idx];
    __half h0, l0, h1, l1;
    split_h(v.x, h0, l0);
    split_h(v.y, h1, l1);
    ((__half2*)(x2 + row*256))[e2]      = __halves2half2(h0, h1);
    ((__half2*)(x2 + row*256 + 128))[e2] = __halves2half2(l0, l1);
}
__global__ void reorder_conv(const float* __restrict__ ck,
                             __half* __restrict__ bx, __half* __restrict__ bh) {
    long idx = (long)blockIdx.x*blockDim.x + threadIdx.x;
    if (idx >= (long)OC*1152) return;
    int oc = idx / 1152, k = idx % 1152;
    int tap = k >> 7, ic = k & 127;
    int ky = tap / 3, kx = tap % 3;
    bx[idx] = __float2half(ck[(((long)oc*256 + ic      )*3 + ky)*3 + kx]);
    bh[idx] = __float2half(ck[(((long)oc*256 + 128 + ic)*3 + ky)*3 + kx]);
}
__global__ void reorder_dense(const float* __restrict__ wp, const float* __restrict__ wi,
                              const float* __restrict__ wo,
                              __half* __restrict__ bp, __half* __restrict__ bi,
                              __half* __restrict__ bo) {
    int idx = blockIdx.x*blockDim.x + threadIdx.x;
    if (idx >= 640*128) return;
    int n = idx >> 7, k = idx & 127;
    const float* w; __half* b; int nn, N;
    if (n < 128)      { w = wp; b = bp; nn = n;       N = 128; }
    else if (n < 512) { w = wi; b = bi; nn = n - 128; N = 384; }
    else              { w = wo; b = bo; nn = n - 512; N = 128; }
    __half v = __float2half(w[k*N + nn]);
    b[nn*256 + k]       = v;
    b[nn*256 + 128 + k] = v;
}

// -------------------- attention core (fp16 qkv in) --------------------
__global__ __launch_bounds__(128)
void attn_core(const __half* __restrict__ qkv, __half* __restrict__ ao) {
    __shared__ float qs[16][384];
    int bid = blockIdx.x;
    int b = bid >> 10, hw = bid & 1023;
    int tid = threadIdx.x;
    for (int idx = tid; idx < 16*192; idx += 128) {
        int t = idx / 192, f = idx % 192;
        __half2 h2 = ((const __half2*)(qkv + ((long)(b*16+t)*1024 + hw)*384))[f];
        float2 f2 = __half22float2(h2);
        qs[t][2*f]   = f2.x;
        qs[t][2*f+1] = f2.y;
    }
    __syncthreads();
    int i = tid >> 4, srow = tid & 15;
    float qd[16];
    #pragma unroll
    for (int d=0; d<16; d++) qd[d] = qs[srow][i*48+d];
    float sc[16];
    float mx = -1e30f;
    #pragma unroll
    for (int l=0;l<16;l++) {
        float sv = 0.f;
        #pragma unroll
        for (int d=0;d<16;d++) sv += qd[d]*qs[l][i*48+16+d];
        sv = sv*0.25f + (l<=srow ? 1.0f : -1000.0f);
        sc[l]=sv; mx = fmaxf(mx, sv);
    }
    float sum=0.f;
    #pragma unroll
    for (int l=0;l<16;l++){ sc[l]=__expf(sc[l]-mx); sum+=sc[l]; }
    float inv = 1.0f/sum;
    float o[16];
    #pragma unroll
    for (int d=0;d<16;d++) o[d]=0.f;
    #pragma unroll
    for (int l=0;l<16;l++) {
        float wl = sc[l]*inv;
        #pragma unroll
        for (int d=0;d<16;d++) o[d] += wl*qs[l][i*48+32+d];
    }
    long t = (long)(b*16+srow)*1024 + hw;
    #pragma unroll
    for (int d=0;d<16;d++) {
        __half hi, lo;
        split_h(o[d], hi, lo);
        ao[t*256 + i*16 + d]       = hi;
        ao[t*256 + 128 + i*16 + d] = lo;
    }
}

// -------------------- universal warp-MMA fp16 GEMM / implicit conv --------------------
// CTA 128x128, 16 warps 32x32, chunks of 64, 4-stage cp.async.
// NTAP=1 dense (A rows 256): NCH chunks (4 = 2-term, 2 = 1-term hi half).
// NTAP=9 conv gather (A rows 128, NCH=18).
// EPI: 2 +residual -> fp16 | 5 silu+LN+split -> [hi|lo]
//      6 store fp16 (with z) | 7 accumulate fp16 (with z)
#define ROWB 144
#define STAGE_A (128*ROWB)
#define STAGE   (2*STAGE_A)
#define NSTAGE  4
#define GEMM_SMEM (NSTAGE*STAGE)  // 147456
#define SREDW 132                 // padded f32 row stride for LN epilogue

template<int NTAP, int NCH, int EPI>
__global__ __launch_bounds__(512, 1)
void gemm_mma(const __half* __restrict__ A, const __half* __restrict__ Bw,
              float* __restrict__ Out, int ldo,
              const float* __restrict__ aux, const float* __restrict__ aux2,
              __half* __restrict__ outh,
              long a_bstride, long a_zstride, long o_zstride) {
    constexpr int ALEN = (NTAP == 9) ? 128 : 256;   // row stride (halfs)
    constexpr int CPT  = ALEN / 64;
    extern __shared__ char smem[];
    uint32_t sb = smem_u32(smem);

    int tid = threadIdx.x;
    int m0 = blockIdx.x * 128;
    int n0 = blockIdx.y * 128;
    int z  = blockIdx.z;

    int lrow = tid >> 2;
    int lseg = (tid & 3) * 2;
    int p = m0 + lrow;
    int bb = p >> 10, pix = p & 1023;
    int y = pix >> 5, x = pix & 31;
    long arow_base = (long)bb * a_bstride + (long)z * a_zstride;

    auto load_chunk = [&](int c, int st) {
        int koff = (c % CPT) * 64;
        bool v = true;
        long arow;
        if (NTAP == 9) {
            int tap = c / CPT;
            int ky = tap/3 - 1, kx = tap%3 - 1;
            int yy = y + ky, xx = x + kx;
            v = ((unsigned)yy < 32u) && ((unsigned)xx < 32u);
            arow = arow_base + ((yy<<5) + xx);
        } else {
            arow = arow_base + pix;
        }
        const __half* asrc = v ? (A + arow*ALEN + koff + lseg*8) : A;
        uint32_t ab = sb + st*STAGE + lrow*ROWB + lseg*16;
        cp16(ab,      asrc,     v);
        cp16(ab + 16, asrc + 8, v);
        const __half* bsrc = Bw + (long)(n0 + lrow)*(NTAP*ALEN) + c*64 + lseg*8;
        uint32_t bbs = sb + st*STAGE + STAGE_A + lrow*ROWB + lseg*16;
        cp16(bbs,      bsrc,     true);
        cp16(bbs + 16, bsrc + 8, true);
        CP_COMMIT();
    };

    int w = tid >> 5, l = tid & 31;
    int m_off = (w >> 2) * 32;
    int n_off = (w & 3) * 32;
    int lr = l & 15, lh = (l >> 4) << 4;

    float acc[2][4][4];
    #pragma unroll
    for (int i=0;i<2;i++)
        #pragma unroll
        for (int j=0;j<4;j++)
            #pragma unroll
            for (int q=0;q<4;q++) acc[i][j][q]=0.f;

    load_chunk(0, 0);
    if (NCH > 1) load_chunk(1, 1); else CP_COMMIT();
    if (NCH > 2) load_chunk(2, 2); else CP_COMMIT();

    for (int c = 0; c < NCH; c++) {
        int st = c & (NSTAGE-1);
        if (c + 3 < NCH) load_chunk(c + 3, (c + 3) & (NSTAGE-1));
        else CP_COMMIT();
        CP_WAIT3();
        __syncthreads();

        uint32_t a_st = sb + st*STAGE;
        uint32_t b_st = a_st + STAGE_A;
        #pragma unroll
        for (int ks = 0; ks < 4; ks++) {
            uint32_t af[2][4], bf[2][4];
            #pragma unroll
            for (int mt = 0; mt < 2; mt++)
                ldm_x4(af[mt], a_st + (m_off + mt*16 + lr)*ROWB + ks*32 + lh);
            #pragma unroll
            for (int nt = 0; nt < 2; nt++)
                ldm_x4(bf[nt], b_st + (n_off + nt*16 + lr)*ROWB + ks*32 + lh);
            #pragma unroll
            for (int mt = 0; mt < 2; mt++) {
                #pragma unroll
                for (int n8 = 0; n8 < 4; n8++) {
                    int nt = n8 >> 1, hi = n8 & 1;
                    mma16816(acc[mt][n8], af[mt], bf[nt][hi], bf[nt][2+hi]);
                }
            }
        }
        __syncthreads();
    }

    if (EPI == 5) {
        // silu into padded smem (CTA owns full rows: N=128, n0=0)
        float* sred = (float*)smem;
        #pragma unroll
        for (int mt = 0; mt < 2; mt++) {
            int r0 = m_off + mt*16 + (l >> 2);
            #pragma unroll
            for (int n8 = 0; n8 < 4; n8++) {
                int cc = n_off + n8*8 + (l & 3)*2;
                #pragma unroll
                for (int q = 0; q < 4; q++) {
                    float v = acc[mt][n8][q];
                    v = v / (1.0f + __expf(-v));
                    sred[(r0 + (q>>1)*8)*SREDW + cc + (q&1)] = v;
                }
            }
        }
        __syncthreads();
        // LN: warp-per-row (8 rows/warp), conflict-free strided reads
        #pragma unroll
        for (int rr = 0; rr < 8; rr++) {
            int row = w*8 + rr;
            float v4[4];
            float s = 0.f, qs = 0.f;
            #pragma unroll
            for (int j = 0; j < 4; j++) {
                float v = sred[row*SREDW + l + j*32];
                v4[j] = v; s += v; qs += v*v;
            }
            #pragma unroll
            for (int off = 16; off; off >>= 1) {
                s  += __shfl_xor_sync(0xffffffff, s, off);
                qs += __shfl_xor_sync(0xffffffff, qs, off);
            }
            float mu = s * (1.0f/128.0f);
            float rs = rsqrtf(qs * (1.0f/128.0f) - mu*mu + 1e-5f);
            long grow = m0 + row;
            #pragma unroll
            for (int j = 0; j < 4; j++) {
                int e = l + j*32;
                float v = (v4[j] - mu) * rs * aux[e] + aux2[e];
                __half hi, lo;
                split_h(v, hi, lo);
                outh[grow*256 + e]       = hi;
                outh[grow*256 + 128 + e] = lo;
            }
        }
        return;
    }

    #pragma unroll
    for (int mt = 0; mt < 2; mt++) {
        int r0 = m0 + m_off + mt*16 + (l >> 2);
        #pragma unroll
        for (int n8 = 0; n8 < 4; n8++) {
            int cc = n0 + n_off + n8*8 + (l & 3)*2;
            float d0 = acc[mt][n8][0], d1 = acc[mt][n8][1];
            float d2 = acc[mt][n8][2], d3 = acc[mt][n8][3];
            if (EPI == 2) {
                float v0 = d0 + aux[(long)r0*128 + cc];
                float v1 = d1 + aux[(long)r0*128 + cc + 1];
                float v2 = d2 + aux[(long)(r0+8)*128 + cc];
                float v3 = d3 + aux[(long)(r0+8)*128 + cc + 1];
                outh[(long)r0*128 + cc]         = __float2half(v0);
                outh[(long)r0*128 + cc + 1]     = __float2half(v1);
                outh[(long)(r0+8)*128 + cc]     = __float2half(v2);
                outh[(long)(r0+8)*128 + cc + 1] = __float2half(v3);
            } else {  // EPI 6 store / 7 accumulate, fp16, z-offset
                __half* q0 = outh + ((long)z*o_zstride + r0    )*ldo + cc;
                __half* q1 = outh + ((long)z*o_zstride + r0 + 8)*ldo + cc;
                if (EPI == 7) {
                    d0 += __half2float(q0[0]); d1 += __half2float(q0[1]);
                    d2 += __half2float(q1[0]); d3 += __half2float(q1[1]);
                }
                q0[0] = __float2half(d0); q0[1] = __float2half(d1);
                q1[0] = __float2half(d2); q1[1] = __float2half(d3);
            }
        }
    }
}

// -------------------- LSTM gates (fp16 cc, half2 vectorized) --------------------
__global__ void gates_kernel(const __half* __restrict__ cc,
                             float* __restrict__ cbuf,
                             __half* __restrict__ hp,
                             float* __restrict__ out, int s, int czero) {
    int idx = blockIdx.x*blockDim.x + threadIdx.x;
    if (idx >= Pn*64) return;
    int p = idx >> 6, e2 = idx & 63;
    const __half2* row = (const __half2*)(cc + (long)p*OC);
    float2 ci = __half22float2(row[e2]);
    float2 cf = __half22float2(row[64  + e2]);
    float2 co = __half22float2(row[128 + e2]);
    float2 cg = __half22float2(row[192 + e2]);
    float2* crow = (float2*)(cbuf + (long)p*128);
    float2 cp = czero ? make_float2(0.f, 0.f) : crow[e2];
    float si0 = 1.f/(1.f+__expf(-ci.x)), si1 = 1.f/(1.f+__expf(-ci.y));
    float sf0 = 1.f/(1.f+__expf(-cf.x)), sf1 = 1.f/(1.f+__expf(-cf.y));
    float so0 = 1.f/(1.f+__expf(-co.x)), so1 = 1.f/(1.f+__expf(-co.y));
    float cn0 = sf0*cp.x + si0*tanhf(cg.x);
    float cn1 = sf1*cp.y + si1*tanhf(cg.y);
    float h0 = so0*tanhf(cn0);
    float h1 = so1*tanhf(cn1);
    crow[e2] = make_float2(cn0, cn1);
    ((__half2*)(hp + (long)p*128))[e2] = __halves2half2(__float2half(h0), __float2half(h1));
    int b = p >> 10, pix = p & 1023;
    ((float2*)(out + ((long)(b*16+s)*1024 + pix)*128))[e2] = make_float2(h0, h1);
}

// -------------------- launch --------------------
extern "C" void kernel_launch(void* const* d_in, const int* in_sizes, int n_in,
                              void* d_out, int out_size) {
    const float* inputs  = (const float*)d_in[0];
    const float* W_proj  = (const float*)d_in[1];
    const float* ln_g    = (const float*)d_in[2];
    const float* ln_b    = (const float*)d_in[3];
    const float* W_in    = (const float*)d_in[4];
    const float* W_out   = (const float*)d_in[5];
    const float* conv_k  = (const float*)d_in[6];
    float* out = (float*)d_out;

    float *cb;
    __half *ccx, *qkvh, *xin2, *xs2, *ao, *xp, *hp, *bx, *bh, *bproj, *bqkv, *bout;
    cudaGetSymbolAddress((void**)&ccx, g_ccx);
    cudaGetSymbolAddress((void**)&cb,  g_c);
    cudaGetSymbolAddress((void**)&qkvh, g_qkvh);
    cudaGetSymbolAddress((void**)&xin2, g_xin2);
    cudaGetSymbolAddress((void**)&xs2, g_xs2);
    cudaGetSymbolAddress((void**)&ao,  g_ao);
    cudaGetSymbolAddress((void**)&xp,  g_xp);
    cudaGetSymbolAddress((void**)&hp,  g_hp);
    cudaGetSymbolAddress((void**)&bx,  g_bx);
    cudaGetSymbolAddress((void**)&bh,  g_bh);
    cudaGetSymbolAddress((void**)&bproj, g_bproj);
    cudaGetSymbolAddress((void**)&bqkv, g_bqkv);
    cudaGetSymbolAddress((void**)&bout, g_bout);

    cudaFuncSetAttribute((void*)gemm_mma<1,4,5>, cudaFuncAttributeMaxDynamicSharedMemorySize, GEMM_SMEM);
    cudaFuncSetAttribute((void*)gemm_mma<1,2,6>, cudaFuncAttributeMaxDynamicSharedMemorySize, GEMM_SMEM);
    cudaFuncSetAttribute((void*)gemm_mma<1,4,2>, cudaFuncAttributeMaxDynamicSharedMemorySize, GEMM_SMEM);
    cudaFuncSetAttribute((void*)gemm_mma<9,18,6>, cudaFuncAttributeMaxDynamicSharedMemorySize, GEMM_SMEM);
    cudaFuncSetAttribute((void*)gemm_mma<9,18,7>, cudaFuncAttributeMaxDynamicSharedMemorySize, GEMM_SMEM);

    reorder_conv<<<(int)(((long)OC*1152 + 255)/256), 256>>>(conv_k, bx, bh);
    reorder_dense<<<(640*128+255)/256, 256>>>(W_proj, W_in, W_out, bproj, bqkv, bout);
    split_in<<<(int)(((long)TOK*64+255)/256), 256>>>(inputs, xin2);

    // proj + silu + LN fused (2-term), writes xs2 [hi|lo]
    gemm_mma<1,4,5><<<dim3(TOK/128, 1, 1), 512, GEMM_SMEM>>>(
        xin2, bproj, nullptr, 0, ln_g, ln_b, xs2, 1024L, 0L, 0L);

    // qkv = xln @ W_in (1-term, fp16 out)
    gemm_mma<1,2,6><<<dim3(TOK/128, 3, 1), 512, GEMM_SMEM>>>(
        xs2, bqkv, nullptr, 384, nullptr, nullptr, qkvh, 1024L, 0L, 0L);

    attn_core<<<Pn, 128>>>(qkvh, ao);

    // xres = ao @ W_out + inputs -> 1-term fp16 xp
    gemm_mma<1,4,2><<<dim3(TOK/128, 1, 1), 512, GEMM_SMEM>>>(
        ao, bout, nullptr, 0, inputs, nullptr, xp, 1024L, 0L, 0L);

    // batch-parallel conv_x over all 16 steps -> fp16 ccx
    gemm_mma<9,18,6><<<dim3(Pn/128, 4, Sn), 512, GEMM_SMEM>>>(
        xp, bx, nullptr, OC, nullptr, nullptr, ccx, 16384L, 1024L, 8192L);

    // sequential ConvLSTM: conv_h accumulates into fp16 ccx[s]
    for (int s = 0; s < Sn; s++) {
        if (s > 0) {
            gemm_mma<9,18,7><<<dim3(Pn/128, 4, 1), 512, GEMM_SMEM>>>(
                hp, bh, nullptr, OC, nullptr, nullptr, ccx + (long)s*Pn*OC, 1024L, 0L, 0L);
        }
        gates_kernel<<<(Pn*64+255)/256, 256>>>(ccx + (long)s*Pn*OC, cb, hp, out, s, s == 0);
    }
}

// round 12
// speedup vs baseline: 1.4075x; 1.4075x over previous
#include <cuda_runtime.h>
#include <cuda_fp16.h>
#include <cstdint>

// Problem constants
#define Bn 8
#define Sn 16
#define En 128
#define TOK (Bn*Sn*32*32)      // 131072
#define Pn (Bn*32*32)          // 8192
#define OC 512

// -------- scratch (device globals) --------
__device__ float g_ccx[(long)TOK*OC];         // fp32 gate pre-activations
__device__ float g_c[Pn*En];
__device__ __half g_qkvh[(long)TOK*384];
__device__ __half g_xin2[(long)TOK*256];
__device__ __half g_xs2[(long)TOK*256];
__device__ __half g_ao[(long)TOK*128];        // 1-term attention out
__device__ __half g_xp[(long)TOK*128];
__device__ __half g_hp[Pn*128];
__device__ __half g_bx[(long)OC*1152];
__device__ __half g_bh[(long)OC*1152];
__device__ __half g_bproj[128*256];
__device__ __half g_bqkv[384*256];
__device__ __half g_bout[128*128];            // 1-term out-proj weights

// ==================== helpers ====================
__device__ __forceinline__ uint32_t smem_u32(const void* p) {
    uint32_t a;
    asm("{ .reg .u64 t; cvta.to.shared.u64 t, %1; cvt.u32.u64 %0, t; }" : "=r"(a) : "l"(p));
    return a;
}
__device__ __forceinline__ void cp16(uint32_t dst, const void* src, bool pred) {
    asm volatile("cp.async.cg.shared.global [%0], [%1], 16, %2;"
        :: "r"(dst), "l"(src), "r"(pred ? 16u : 0u));
}
#define CP_COMMIT() asm volatile("cp.async.commit_group;" ::: "memory")
#define CP_WAIT3()  asm volatile("cp.async.wait_group 3;" ::: "memory")

__device__ __forceinline__ void ldm_x4(uint32_t* r, uint32_t addr) {
    asm volatile("ldmatrix.sync.aligned.m8n8.x4.shared.b16 {%0,%1,%2,%3}, [%4];"
        : "=r"(r[0]), "=r"(r[1]), "=r"(r[2]), "=r"(r[3]) : "r"(addr));
}
__device__ __forceinline__ void mma16816(float* d, const uint32_t* a, uint32_t b0, uint32_t b1) {
    asm volatile("mma.sync.aligned.m16n8k16.row.col.f32.f16.f16.f32 "
        "{%0,%1,%2,%3}, {%4,%5,%6,%7}, {%8,%9}, {%0,%1,%2,%3};"
        : "+f"(d[0]), "+f"(d[1]), "+f"(d[2]), "+f"(d[3])
        : "r"(a[0]), "r"(a[1]), "r"(a[2]), "r"(a[3]), "r"(b0), "r"(b1));
}
__device__ __forceinline__ void split_h(float x, __half& hi, __half& lo) {
    hi = __float2half(x);
    lo = __float2half(x - __half2float(hi));
}

// -------------------- small kernels --------------------
__global__ void split_in(const float* __restrict__ inp, __half* __restrict__ x2) {
    long idx = (long)blockIdx.x*blockDim.x + threadIdx.x;
    if (idx >= (long)TOK*64) return;
    long row = idx >> 6; int e2 = idx & 63;
    float2 v = ((const float2*)inp)[idx];
    __half h0, l0, h1, l1;
    split_h(v.x, h0, l0);
    split_h(v.y, h1, l1);
    ((__half2*)(x2 + row*256))[e2]      = __halves2half2(h0, h1);
    ((__half2*)(x2 + row*256 + 128))[e2] = __halves2half2(l0, l1);
}
__global__ void reorder_conv(const float* __restrict__ ck,
                             __half* __restrict__ bx, __half* __restrict__ bh) {
    long idx = (long)blockIdx.x*blockDim.x + threadIdx.x;
    if (idx >= (long)OC*1152) return;
    int oc = idx / 1152, k = idx % 1152;
    int tap = k >> 7, ic = k & 127;
    int ky = tap / 3, kx = tap % 3;
    bx[idx] = __float2half(ck[(((long)oc*256 + ic      )*3 + ky)*3 + kx]);
    bh[idx] = __float2half(ck[(((long)oc*256 + 128 + ic)*3 + ky)*3 + kx]);
}
__global__ void reorder_dense(const float* __restrict__ wp, const float* __restrict__ wi,
                              const float* __restrict__ wo,
                              __half* __restrict__ bp, __half* __restrict__ bi,
                              __half* __restrict__ bo) {
    int idx = blockIdx.x*blockDim.x + threadIdx.x;
    if (idx >= 640*128) return;
    int n = idx >> 7, k = idx & 127;
    if (n < 128) {                       // proj: 2-term [w|w]
        __half v = __float2half(wp[k*128 + n]);
        bp[n*256 + k]       = v;
        bp[n*256 + 128 + k] = v;
    } else if (n < 512) {                // qkv: 2-term [w|w]
        int nn = n - 128;
        __half v = __float2half(wi[k*384 + nn]);
        bi[nn*256 + k]       = v;
        bi[nn*256 + 128 + k] = v;
    } else {                             // out: 1-term
        int nn = n - 512;
        bo[nn*128 + k] = __float2half(wo[k*128 + nn]);
    }
}

// -------------------- attention core (fp16 qkv in, 1-term ao out) --------------------
__global__ __launch_bounds__(128)
void attn_core(const __half* __restrict__ qkv, __half* __restrict__ ao) {
    __shared__ float qs[16][384];
    int bid = blockIdx.x;
    int b = bid >> 10, hw = bid & 1023;
    int tid = threadIdx.x;
    for (int idx = tid; idx < 16*192; idx += 128) {
        int t = idx / 192, f = idx % 192;
        __half2 h2 = ((const __half2*)(qkv + ((long)(b*16+t)*1024 + hw)*384))[f];
        float2 f2 = __half22float2(h2);
        qs[t][2*f]   = f2.x;
        qs[t][2*f+1] = f2.y;
    }
    __syncthreads();
    int i = tid >> 4, srow = tid & 15;
    float qd[16];
    #pragma unroll
    for (int d=0; d<16; d++) qd[d] = qs[srow][i*48+d];
    float sc[16];
    float mx = -1e30f;
    #pragma unroll
    for (int l=0;l<16;l++) {
        float sv = 0.f;
        #pragma unroll
        for (int d=0;d<16;d++) sv += qd[d]*qs[l][i*48+16+d];
        sv = sv*0.25f + (l<=srow ? 1.0f : -1000.0f);
        sc[l]=sv; mx = fmaxf(mx, sv);
    }
    float sum=0.f;
    #pragma unroll
    for (int l=0;l<16;l++){ sc[l]=__expf(sc[l]-mx); sum+=sc[l]; }
    float inv = 1.0f/sum;
    float o[16];
    #pragma unroll
    for (int d=0;d<16;d++) o[d]=0.f;
    #pragma unroll
    for (int l=0;l<16;l++) {
        float wl = sc[l]*inv;
        #pragma unroll
        for (int d=0;d<16;d++) o[d] += wl*qs[l][i*48+32+d];
    }
    long t = (long)(b*16+srow)*1024 + hw;
    #pragma unroll
    for (int d=0;d<16;d+=2)
        ((__half2*)(ao + t*128 + i*16))[d>>1] =
            __halves2half2(__float2half(o[d]), __float2half(o[d+1]));
}

// -------------------- universal warp-MMA fp16 GEMM / implicit conv --------------------
// CTA 128x128, 16 warps 32x32, chunks of 64, 4-stage cp.async.
// ALEN = A row stride in halfs; NCH = number of 64-k chunks consumed.
// NTAP=9 conv gather. EPI: 0 store f32 | 1 accumulate f32 | 2 +residual -> fp16
//      5 silu+LN+split -> [hi|lo] | 6 store fp16
#define ROWB 144
#define STAGE_A (128*ROWB)
#define STAGE   (2*STAGE_A)
#define NSTAGE  4
#define GEMM_SMEM (NSTAGE*STAGE)  // 147456
#define SREDW 132                 // padded f32 row stride for LN epilogue

template<int NTAP, int ALEN, int NCH, int EPI>
__global__ __launch_bounds__(512, 1)
void gemm_mma(const __half* __restrict__ A, const __half* __restrict__ Bw,
              float* __restrict__ Out, int ldo,
              const float* __restrict__ aux, const float* __restrict__ aux2,
              __half* __restrict__ outh,
              long a_bstride, long a_zstride, long o_zstride) {
    constexpr int CPT = ALEN / 64;
    extern __shared__ char smem[];
    uint32_t sb = smem_u32(smem);

    int tid = threadIdx.x;
    int m0 = blockIdx.x * 128;
    int n0 = blockIdx.y * 128;
    int z  = blockIdx.z;

    int lrow = tid >> 2;
    int lseg = (tid & 3) * 2;
    int p = m0 + lrow;
    int bb = p >> 10, pix = p & 1023;
    int y = pix >> 5, x = pix & 31;
    long arow_base = (long)bb * a_bstride + (long)z * a_zstride;

    auto load_chunk = [&](int c, int st) {
        int koff = (c % CPT) * 64;
        bool v = true;
        long arow;
        if (NTAP == 9) {
            int tap = c / CPT;
            int ky = tap/3 - 1, kx = tap%3 - 1;
            int yy = y + ky, xx = x + kx;
            v = ((unsigned)yy < 32u) && ((unsigned)xx < 32u);
            arow = arow_base + ((yy<<5) + xx);
        } else {
            arow = arow_base + pix;
        }
        const __half* asrc = v ? (A + arow*ALEN + koff + lseg*8) : A;
        uint32_t ab = sb + st*STAGE + lrow*ROWB + lseg*16;
        cp16(ab,      asrc,     v);
        cp16(ab + 16, asrc + 8, v);
        const __half* bsrc = Bw + (long)(n0 + lrow)*(NTAP*ALEN) + c*64 + lseg*8;
        uint32_t bbs = sb + st*STAGE + STAGE_A + lrow*ROWB + lseg*16;
        cp16(bbs,      bsrc,     true);
        cp16(bbs + 16, bsrc + 8, true);
        CP_COMMIT();
    };

    int w = tid >> 5, l = tid & 31;
    int m_off = (w >> 2) * 32;
    int n_off = (w & 3) * 32;
    int lr = l & 15, lh = (l >> 4) << 4;

    float acc[2][4][4];
    #pragma unroll
    for (int i=0;i<2;i++)
        #pragma unroll
        for (int j=0;j<4;j++)
            #pragma unroll
            for (int q=0;q<4;q++) acc[i][j][q]=0.f;

    load_chunk(0, 0);
    if (NCH > 1) load_chunk(1, 1); else CP_COMMIT();
    if (NCH > 2) load_chunk(2, 2); else CP_COMMIT();

    for (int c = 0; c < NCH; c++) {
        int st = c & (NSTAGE-1);
        if (c + 3 < NCH) load_chunk(c + 3, (c + 3) & (NSTAGE-1));
        else CP_COMMIT();
        CP_WAIT3();
        __syncthreads();

        uint32_t a_st = sb + st*STAGE;
        uint32_t b_st = a_st + STAGE_A;
        #pragma unroll
        for (int ks = 0; ks < 4; ks++) {
            uint32_t af[2][4], bf[2][4];
            #pragma unroll
            for (int mt = 0; mt < 2; mt++)
                ldm_x4(af[mt], a_st + (m_off + mt*16 + lr)*ROWB + ks*32 + lh);
            #pragma unroll
            for (int nt = 0; nt < 2; nt++)
                ldm_x4(bf[nt], b_st + (n_off + nt*16 + lr)*ROWB + ks*32 + lh);
            #pragma unroll
            for (int mt = 0; mt < 2; mt++) {
                #pragma unroll
                for (int n8 = 0; n8 < 4; n8++) {
                    int nt = n8 >> 1, hi = n8 & 1;
                    mma16816(acc[mt][n8], af[mt], bf[nt][hi], bf[nt][2+hi]);
                }
            }
        }
        __syncthreads();
    }

    if (EPI == 5) {
        float* sred = (float*)smem;
        #pragma unroll
        for (int mt = 0; mt < 2; mt++) {
            int r0 = m_off + mt*16 + (l >> 2);
            #pragma unroll
            for (int n8 = 0; n8 < 4; n8++) {
                int cc = n_off + n8*8 + (l & 3)*2;
                #pragma unroll
                for (int q = 0; q < 4; q++) {
                    float v = acc[mt][n8][q];
                    v = v / (1.0f + __expf(-v));
                    sred[(r0 + (q>>1)*8)*SREDW + cc + (q&1)] = v;
                }
            }
        }
        __syncthreads();
        #pragma unroll
        for (int rr = 0; rr < 8; rr++) {
            int row = w*8 + rr;
            float v4[4];
            float s = 0.f, qs = 0.f;
            #pragma unroll
            for (int j = 0; j < 4; j++) {
                float v = sred[row*SREDW + l + j*32];
                v4[j] = v; s += v; qs += v*v;
            }
            #pragma unroll
            for (int off = 16; off; off >>= 1) {
                s  += __shfl_xor_sync(0xffffffff, s, off);
                qs += __shfl_xor_sync(0xffffffff, qs, off);
            }
            float mu = s * (1.0f/128.0f);
            float rs = rsqrtf(qs * (1.0f/128.0f) - mu*mu + 1e-5f);
            long grow = m0 + row;
            #pragma unroll
            for (int j = 0; j < 4; j++) {
                int e = l + j*32;
                float v = (v4[j] - mu) * rs * aux[e] + aux2[e];
                __half hi, lo;
                split_h(v, hi, lo);
                outh[grow*256 + e]       = hi;
                outh[grow*256 + 128 + e] = lo;
            }
        }
        return;
    }

    #pragma unroll
    for (int mt = 0; mt < 2; mt++) {
        int r0 = m0 + m_off + mt*16 + (l >> 2);
        #pragma unroll
        for (int n8 = 0; n8 < 4; n8++) {
            int cc = n0 + n_off + n8*8 + (l & 3)*2;
            float d0 = acc[mt][n8][0], d1 = acc[mt][n8][1];
            float d2 = acc[mt][n8][2], d3 = acc[mt][n8][3];
            if (EPI == 2) {
                float v0 = d0 + aux[(long)r0*128 + cc];
                float v1 = d1 + aux[(long)r0*128 + cc + 1];
                float v2 = d2 + aux[(long)(r0+8)*128 + cc];
                float v3 = d3 + aux[(long)(r0+8)*128 + cc + 1];
                outh[(long)r0*128 + cc]         = __float2half(v0);
                outh[(long)r0*128 + cc + 1]     = __float2half(v1);
                outh[(long)(r0+8)*128 + cc]     = __float2half(v2);
                outh[(long)(r0+8)*128 + cc + 1] = __float2half(v3);
            } else if (EPI == 6) {
                __half* q0 = outh + (long)r0*ldo + cc;
                __half* q1 = outh + (long)(r0+8)*ldo + cc;
                q0[0] = __float2half(d0); q0[1] = __float2half(d1);
                q1[0] = __float2half(d2); q1[1] = __float2half(d3);
            } else {
                float* p0 = Out + ((long)z*o_zstride + r0    )*ldo + cc;
                float* p1 = Out + ((long)z*o_zstride + r0 + 8)*ldo + cc;
                if (EPI == 1) { d0 += p0[0]; d1 += p0[1]; d2 += p1[0]; d3 += p1[1]; }
                p0[0] = d0; p0[1] = d1;
                p1[0] = d2; p1[1] = d3;
            }
        }
    }
}

// -------------------- LSTM gates --------------------
__global__ void gates_kernel(const float* __restrict__ cc,
                             float* __restrict__ cbuf,
                             __half* __restrict__ hp,
                             float* __restrict__ out, int s, int czero) {
    int idx = blockIdx.x*blockDim.x + threadIdx.x;
    if (idx >= Pn*En) return;
    int p = idx >> 7, e = idx & 127;
    const float* row = cc + (long)p*OC;
    float ci = row[e], cf = row[128+e], co = row[256+e], cg = row[384+e];
    float si = 1.f/(1.f+__expf(-ci));
    float sf = 1.f/(1.f+__expf(-cf));
    float so = 1.f/(1.f+__expf(-co));
    float c_prev = czero ? 0.f : cbuf[idx];
    float c_next = sf*c_prev + si*tanhf(cg);
    float h_next = so*tanhf(c_next);
    cbuf[idx] = c_next;
    hp[(long)p*128 + e] = __float2half(h_next);
    int b = p >> 10, pix = p & 1023;
    out[((long)(b*16+s)*1024 + pix)*128 + e] = h_next;
}

// -------------------- launch --------------------
extern "C" void kernel_launch(void* const* d_in, const int* in_sizes, int n_in,
                              void* d_out, int out_size) {
    const float* inputs  = (const float*)d_in[0];
    const float* W_proj  = (const float*)d_in[1];
    const float* ln_g    = (const float*)d_in[2];
    const float* ln_b    = (const float*)d_in[3];
    const float* W_in    = (const float*)d_in[4];
    const float* W_out   = (const float*)d_in[5];
    const float* conv_k  = (const float*)d_in[6];
    float* out = (float*)d_out;

    float *ccx, *cb;
    __half *qkvh, *xin2, *xs2, *ao, *xp, *hp, *bx, *bh, *bproj, *bqkv, *bout;
    cudaGetSymbolAddress((void**)&ccx, g_ccx);
    cudaGetSymbolAddress((void**)&cb,  g_c);
    cudaGetSymbolAddress((void**)&qkvh, g_qkvh);
    cudaGetSymbolAddress((void**)&xin2, g_xin2);
    cudaGetSymbolAddress((void**)&xs2, g_xs2);
    cudaGetSymbolAddress((void**)&ao,  g_ao);
    cudaGetSymbolAddress((void**)&xp,  g_xp);
    cudaGetSymbolAddress((void**)&hp,  g_hp);
    cudaGetSymbolAddress((void**)&bx,  g_bx);
    cudaGetSymbolAddress((void**)&bh,  g_bh);
    cudaGetSymbolAddress((void**)&bproj, g_bproj);
    cudaGetSymbolAddress((void**)&bqkv, g_bqkv);
    cudaGetSymbolAddress((void**)&bout, g_bout);

    cudaFuncSetAttribute((void*)gemm_mma<1,256,4,5>, cudaFuncAttributeMaxDynamicSharedMemorySize, GEMM_SMEM);
    cudaFuncSetAttribute((void*)gemm_mma<1,256,2,6>, cudaFuncAttributeMaxDynamicSharedMemorySize, GEMM_SMEM);
    cudaFuncSetAttribute((void*)gemm_mma<1,128,2,2>, cudaFuncAttributeMaxDynamicSharedMemorySize, GEMM_SMEM);
    cudaFuncSetAttribute((void*)gemm_mma<9,128,18,0>, cudaFuncAttributeMaxDynamicSharedMemorySize, GEMM_SMEM);
    cudaFuncSetAttribute((void*)gemm_mma<9,128,18,1>, cudaFuncAttributeMaxDynamicSharedMemorySize, GEMM_SMEM);

    reorder_conv<<<(int)(((long)OC*1152 + 255)/256), 256>>>(conv_k, bx, bh);
    reorder_dense<<<(640*128+255)/256, 256>>>(W_proj, W_in, W_out, bproj, bqkv, bout);
    split_in<<<(int)(((long)TOK*64+255)/256), 256>>>(inputs, xin2);

    // proj + silu + LN fused (2-term), writes xs2 [hi|lo]
    gemm_mma<1,256,4,5><<<dim3(TOK/128, 1, 1), 512, GEMM_SMEM>>>(
        xin2, bproj, nullptr, 0, ln_g, ln_b, xs2, 1024L, 0L, 0L);

    // qkv = xln @ W_in (1-term, fp16 out)
    gemm_mma<1,256,2,6><<<dim3(TOK/128, 3, 1), 512, GEMM_SMEM>>>(
        xs2, bqkv, nullptr, 384, nullptr, nullptr, qkvh, 1024L, 0L, 0L);

    attn_core<<<Pn, 128>>>(qkvh, ao);

    // xres = ao @ W_out + inputs -> 1-term fp16 xp  (1-term ao, K'=128)
    gemm_mma<1,128,2,2><<<dim3(TOK/128, 1, 1), 512, GEMM_SMEM>>>(
        ao, bout, nullptr, 0, inputs, nullptr, xp, 1024L, 0L, 0L);

    // batch-parallel conv_x over all 16 steps (1-term)
    gemm_mma<9,128,18,0><<<dim3(Pn/128, 4, Sn), 512, GEMM_SMEM>>>(
        xp, bx, ccx, OC, nullptr, nullptr, nullptr, 16384L, 1024L, 8192L);

    // sequential ConvLSTM
    for (int s = 0; s < Sn; s++) {
        if (s > 0) {
            gemm_mma<9,128,18,1><<<dim3(Pn/128, 4, 1), 512, GEMM_SMEM>>>(
                hp, bh, ccx + (long)s*Pn*OC, OC, nullptr, nullptr, nullptr, 1024L, 0L, 0L);
        }
        gates_kernel<<<(Pn*En+255)/256, 256>>>(ccx + (long)s*Pn*OC, cb, hp, out, s, s == 0);
    }
}

// round 13
// speedup vs baseline: 1.5030x; 1.0678x over previous
#include <cuda_runtime.h>
#include <cuda_fp16.h>
#include <cstdint>

// Problem constants
#define Bn 8
#define Sn 16
#define En 128
#define TOK (Bn*Sn*32*32)      // 131072
#define Pn (Bn*32*32)          // 8192
#define OC 512

// -------- scratch (device globals) --------
__device__ float g_ccx[(long)TOK*OC];         // fp32 gate pre-activations
__device__ float g_c[Pn*En];
__device__ __half g_qkvh[(long)TOK*384];
__device__ __half g_xin2[(long)TOK*256];
__device__ __half g_xs2[(long)TOK*256];
__device__ __half g_ao[(long)TOK*128];        // 1-term attention out
__device__ __half g_xp[(long)TOK*128];
__device__ __half g_hp[Pn*128];
__device__ __half g_bx[(long)OC*1152];
__device__ __half g_bh[(long)OC*1152];
__device__ __half g_bproj[128*256];
__device__ __half g_bqkv[384*256];
__device__ __half g_bout[128*128];            // 1-term out-proj weights

// ==================== helpers ====================
__device__ __forceinline__ uint32_t smem_u32(const void* p) {
    uint32_t a;
    asm("{ .reg .u64 t; cvta.to.shared.u64 t, %1; cvt.u32.u64 %0, t; }" : "=r"(a) : "l"(p));
    return a;
}
__device__ __forceinline__ void cp16(uint32_t dst, const void* src, bool pred) {
    asm volatile("cp.async.cg.shared.global [%0], [%1], 16, %2;"
        :: "r"(dst), "l"(src), "r"(pred ? 16u : 0u));
}
#define CP_COMMIT() asm volatile("cp.async.commit_group;" ::: "memory")
#define CP_WAIT3()  asm volatile("cp.async.wait_group 3;" ::: "memory")

__device__ __forceinline__ void ldm_x4(uint32_t* r, uint32_t addr) {
    asm volatile("ldmatrix.sync.aligned.m8n8.x4.shared.b16 {%0,%1,%2,%3}, [%4];"
        : "=r"(r[0]), "=r"(r[1]), "=r"(r[2]), "=r"(r[3]) : "r"(addr));
}
__device__ __forceinline__ void mma16816(float* d, const uint32_t* a, uint32_t b0, uint32_t b1) {
    asm volatile("mma.sync.aligned.m16n8k16.row.col.f32.f16.f16.f32 "
        "{%0,%1,%2,%3}, {%4,%5,%6,%7}, {%8,%9}, {%0,%1,%2,%3};"
        : "+f"(d[0]), "+f"(d[1]), "+f"(d[2]), "+f"(d[3])
        : "r"(a[0]), "r"(a[1]), "r"(a[2]), "r"(a[3]), "r"(b0), "r"(b1));
}
__device__ __forceinline__ void split_h(float x, __half& hi, __half& lo) {
    hi = __float2half(x);
    lo = __float2half(x - __half2float(hi));
}

// -------------------- small kernels --------------------
__global__ void split_in(const float* __restrict__ inp, __half* __restrict__ x2) {
    long idx = (long)blockIdx.x*blockDim.x + threadIdx.x;
    if (idx >= (long)TOK*64) return;
    long row = idx >> 6; int e2 = idx & 63;
    float2 v = ((const float2*)inp)[idx];
    __half h0, l0, h1, l1;
    split_h(v.x, h0, l0);
    split_h(v.y, h1, l1);
    ((__half2*)(x2 + row*256))[e2]      = __halves2half2(h0, h1);
    ((__half2*)(x2 + row*256 + 128))[e2] = __halves2half2(l0, l1);
}
__global__ void reorder_conv(const float* __restrict__ ck,
                             __half* __restrict__ bx, __half* __restrict__ bh) {
    long idx = (long)blockIdx.x*blockDim.x + threadIdx.x;
    if (idx >= (long)OC*1152) return;
    int oc = idx / 1152, k = idx % 1152;
    int tap = k >> 7, ic = k & 127;
    int ky = tap / 3, kx = tap % 3;
    bx[idx] = __float2half(ck[(((long)oc*256 + ic      )*3 + ky)*3 + kx]);
    bh[idx] = __float2half(ck[(((long)oc*256 + 128 + ic)*3 + ky)*3 + kx]);
}
__global__ void reorder_dense(const float* __restrict__ wp, const float* __restrict__ wi,
                              const float* __restrict__ wo,
                              __half* __restrict__ bp, __half* __restrict__ bi,
                              __half* __restrict__ bo) {
    int idx = blockIdx.x*blockDim.x + threadIdx.x;
    if (idx >= 640*128) return;
    int n = idx >> 7, k = idx & 127;
    if (n < 128) {                       // proj: 2-term [w|w]
        __half v = __float2half(wp[k*128 + n]);
        bp[n*256 + k]       = v;
        bp[n*256 + 128 + k] = v;
    } else if (n < 512) {                // qkv: 2-term [w|w]
        int nn = n - 128;
        __half v = __float2half(wi[k*384 + nn]);
        bi[nn*256 + k]       = v;
        bi[nn*256 + 128 + k] = v;
    } else {                             // out: 1-term
        int nn = n - 512;
        bo[nn*128 + k] = __float2half(wo[k*128 + nn]);
    }
}

// -------------------- attention core (fp16 qkv in, 1-term ao out) --------------------
__global__ __launch_bounds__(128)
void attn_core(const __half* __restrict__ qkv, __half* __restrict__ ao) {
    __shared__ float qs[16][384];
    int bid = blockIdx.x;
    int b = bid >> 10, hw = bid & 1023;
    int tid = threadIdx.x;
    for (int idx = tid; idx < 16*192; idx += 128) {
        int t = idx / 192, f = idx % 192;
        __half2 h2 = ((const __half2*)(qkv + ((long)(b*16+t)*1024 + hw)*384))[f];
        float2 f2 = __half22float2(h2);
        qs[t][2*f]   = f2.x;
        qs[t][2*f+1] = f2.y;
    }
    __syncthreads();
    int i = tid >> 4, srow = tid & 15;
    float qd[16];
    #pragma unroll
    for (int d=0; d<16; d++) qd[d] = qs[srow][i*48+d];
    float sc[16];
    float mx = -1e30f;
    #pragma unroll
    for (int l=0;l<16;l++) {
        float sv = 0.f;
        #pragma unroll
        for (int d=0;d<16;d++) sv += qd[d]*qs[l][i*48+16+d];
        sv = sv*0.25f + (l<=srow ? 1.0f : -1000.0f);
        sc[l]=sv; mx = fmaxf(mx, sv);
    }
    float sum=0.f;
    #pragma unroll
    for (int l=0;l<16;l++){ sc[l]=__expf(sc[l]-mx); sum+=sc[l]; }
    float inv = 1.0f/sum;
    float o[16];
    #pragma unroll
    for (int d=0;d<16;d++) o[d]=0.f;
    #pragma unroll
    for (int l=0;l<16;l++) {
        float wl = sc[l]*inv;
        #pragma unroll
        for (int d=0;d<16;d++) o[d] += wl*qs[l][i*48+32+d];
    }
    long t = (long)(b*16+srow)*1024 + hw;
    #pragma unroll
    for (int d=0;d<16;d+=2)
        ((__half2*)(ao + t*128 + i*16))[d>>1] =
            __halves2half2(__float2half(o[d]), __float2half(o[d+1]));
}

// -------------------- universal warp-MMA fp16 GEMM / implicit conv --------------------
// CTA 128x128, 16 warps 32x32, chunks of 64, 4-stage cp.async.
// ALEN = A row stride in halfs; NCH = number of 64-k chunks consumed.
// NTAP=9 conv gather. EPI: 0 store f32 | 1 accumulate f32 | 2 +residual -> fp16
//      5 silu+LN+split -> [hi|lo] | 6 store fp16
#define ROWB 144
#define STAGE_A (128*ROWB)
#define STAGE   (2*STAGE_A)
#define NSTAGE  4
#define GEMM_SMEM (NSTAGE*STAGE)  // 147456
#define SREDW 132                 // padded f32 row stride for LN epilogue

template<int NTAP, int ALEN, int NCH, int EPI>
__global__ __launch_bounds__(512, 1)
void gemm_mma(const __half* __restrict__ A, const __half* __restrict__ Bw,
              float* __restrict__ Out, int ldo,
              const float* __restrict__ aux, const float* __restrict__ aux2,
              __half* __restrict__ outh,
              long a_bstride, long a_zstride, long o_zstride) {
    constexpr int CPT = ALEN / 64;
    extern __shared__ char smem[];
    uint32_t sb = smem_u32(smem);

    int tid = threadIdx.x;
    int m0 = blockIdx.x * 128;
    int n0 = blockIdx.y * 128;
    int z  = blockIdx.z;

    int lrow = tid >> 2;
    int lseg = (tid & 3) * 2;
    int p = m0 + lrow;
    int bb = p >> 10, pix = p & 1023;
    int y = pix >> 5, x = pix & 31;
    long arow_base = (long)bb * a_bstride + (long)z * a_zstride;

    auto load_chunk = [&](int c, int st) {
        int koff = (c % CPT) * 64;
        bool v = true;
        long arow;
        if (NTAP == 9) {
            int tap = c / CPT;
            int ky = tap/3 - 1, kx = tap%3 - 1;
            int yy = y + ky, xx = x + kx;
            v = ((unsigned)yy < 32u) && ((unsigned)xx < 32u);
            arow = arow_base + ((yy<<5) + xx);
        } else {
            arow = arow_base + pix;
        }
        const __half* asrc = v ? (A + arow*ALEN + koff + lseg*8) : A;
        uint32_t ab = sb + st*STAGE + lrow*ROWB + lseg*16;
        cp16(ab,      asrc,     v);
        cp16(ab + 16, asrc + 8, v);
        const __half* bsrc = Bw + (long)(n0 + lrow)*(NTAP*ALEN) + c*64 + lseg*8;
        uint32_t bbs = sb + st*STAGE + STAGE_A + lrow*ROWB + lseg*16;
        cp16(bbs,      bsrc,     true);
        cp16(bbs + 16, bsrc + 8, true);
        CP_COMMIT();
    };

    int w = tid >> 5, l = tid & 31;
    int m_off = (w >> 2) * 32;
    int n_off = (w & 3) * 32;
    int lr = l & 15, lh = (l >> 4) << 4;

    float acc[2][4][4];
    #pragma unroll
    for (int i=0;i<2;i++)
        #pragma unroll
        for (int j=0;j<4;j++)
            #pragma unroll
            for (int q=0;q<4;q++) acc[i][j][q]=0.f;

    load_chunk(0, 0);
    if (NCH > 1) load_chunk(1, 1); else CP_COMMIT();
    if (NCH > 2) load_chunk(2, 2); else CP_COMMIT();

    for (int c = 0; c < NCH; c++) {
        int st = c & (NSTAGE-1);
        if (c + 3 < NCH) load_chunk(c + 3, (c + 3) & (NSTAGE-1));
        else CP_COMMIT();
        CP_WAIT3();
        __syncthreads();

        uint32_t a_st = sb + st*STAGE;
        uint32_t b_st = a_st + STAGE_A;
        #pragma unroll
        for (int ks = 0; ks < 4; ks++) {
            uint32_t af[2][4], bf[2][4];
            #pragma unroll
            for (int mt = 0; mt < 2; mt++)
                ldm_x4(af[mt], a_st + (m_off + mt*16 + lr)*ROWB + ks*32 + lh);
            #pragma unroll
            for (int nt = 0; nt < 2; nt++)
                ldm_x4(bf[nt], b_st + (n_off + nt*16 + lr)*ROWB + ks*32 + lh);
            #pragma unroll
            for (int mt = 0; mt < 2; mt++) {
                #pragma unroll
                for (int n8 = 0; n8 < 4; n8++) {
                    int nt = n8 >> 1, hi = n8 & 1;
                    mma16816(acc[mt][n8], af[mt], bf[nt][hi], bf[nt][2+hi]);
                }
            }
        }
        __syncthreads();
    }

    if (EPI == 5) {
        float* sred = (float*)smem;
        #pragma unroll
        for (int mt = 0; mt < 2; mt++) {
            int r0 = m_off + mt*16 + (l >> 2);
            #pragma unroll
            for (int n8 = 0; n8 < 4; n8++) {
                int cc = n_off + n8*8 + (l & 3)*2;
                #pragma unroll
                for (int q = 0; q < 4; q++) {
                    float v = acc[mt][n8][q];
                    v = v / (1.0f + __expf(-v));
                    sred[(r0 + (q>>1)*8)*SREDW + cc + (q&1)] = v;
                }
            }
        }
        __syncthreads();
        #pragma unroll
        for (int rr = 0; rr < 8; rr++) {
            int row = w*8 + rr;
            float v4[4];
            float s = 0.f, qs = 0.f;
            #pragma unroll
            for (int j = 0; j < 4; j++) {
                float v = sred[row*SREDW + l + j*32];
                v4[j] = v; s += v; qs += v*v;
            }
            #pragma unroll
            for (int off = 16; off; off >>= 1) {
                s  += __shfl_xor_sync(0xffffffff, s, off);
                qs += __shfl_xor_sync(0xffffffff, qs, off);
            }
            float mu = s * (1.0f/128.0f);
            float rs = rsqrtf(qs * (1.0f/128.0f) - mu*mu + 1e-5f);
            long grow = m0 + row;
            #pragma unroll
            for (int j = 0; j < 4; j++) {
                int e = l + j*32;
                float v = (v4[j] - mu) * rs * aux[e] + aux2[e];
                __half hi, lo;
                split_h(v, hi, lo);
                outh[grow*256 + e]       = hi;
                outh[grow*256 + 128 + e] = lo;
            }
        }
        return;
    }

    #pragma unroll
    for (int mt = 0; mt < 2; mt++) {
        int r0 = m0 + m_off + mt*16 + (l >> 2);
        #pragma unroll
        for (int n8 = 0; n8 < 4; n8++) {
            int cc = n0 + n_off + n8*8 + (l & 3)*2;
            float d0 = acc[mt][n8][0], d1 = acc[mt][n8][1];
            float d2 = acc[mt][n8][2], d3 = acc[mt][n8][3];
            if (EPI == 2) {
                float v0 = d0 + aux[(long)r0*128 + cc];
                float v1 = d1 + aux[(long)r0*128 + cc + 1];
                float v2 = d2 + aux[(long)(r0+8)*128 + cc];
                float v3 = d3 + aux[(long)(r0+8)*128 + cc + 1];
                outh[(long)r0*128 + cc]         = __float2half(v0);
                outh[(long)r0*128 + cc + 1]     = __float2half(v1);
                outh[(long)(r0+8)*128 + cc]     = __float2half(v2);
                outh[(long)(r0+8)*128 + cc + 1] = __float2half(v3);
            } else if (EPI == 6) {
                __half* q0 = outh + (long)r0*ldo + cc;
                __half* q1 = outh + (long)(r0+8)*ldo + cc;
                q0[0] = __float2half(d0); q0[1] = __float2half(d1);
                q1[0] = __float2half(d2); q1[1] = __float2half(d3);
            } else {
                float* p0 = Out + ((long)z*o_zstride + r0    )*ldo + cc;
                float* p1 = Out + ((long)z*o_zstride + r0 + 8)*ldo + cc;
                if (EPI == 1) { d0 += p0[0]; d1 += p0[1]; d2 += p1[0]; d3 += p1[1]; }
                p0[0] = d0; p0[1] = d1;
                p1[0] = d2; p1[1] = d3;
            }
        }
    }
}

// -------------------- LSTM gates --------------------
__global__ void gates_kernel(const float* __restrict__ cc,
                             float* __restrict__ cbuf,
                             __half* __restrict__ hp,
                             float* __restrict__ out, int s, int czero) {
    int idx = blockIdx.x*blockDim.x + threadIdx.x;
    if (idx >= Pn*En) return;
    int p = idx >> 7, e = idx & 127;
    const float* row = cc + (long)p*OC;
    float ci = row[e], cf = row[128+e], co = row[256+e], cg = row[384+e];
    float si = 1.f/(1.f+__expf(-ci));
    float sf = 1.f/(1.f+__expf(-cf));
    float so = 1.f/(1.f+__expf(-co));
    float c_prev = czero ? 0.f : cbuf[idx];
    float c_next = sf*c_prev + si*tanhf(cg);
    float h_next = so*tanhf(c_next);
    cbuf[idx] = c_next;
    hp[(long)p*128 + e] = __float2half(h_next);
    int b = p >> 10, pix = p & 1023;
    out[((long)(b*16+s)*1024 + pix)*128 + e] = h_next;
}

// -------------------- launch --------------------
extern "C" void kernel_launch(void* const* d_in, const int* in_sizes, int n_in,
                              void* d_out, int out_size) {
    const float* inputs  = (const float*)d_in[0];
    const float* W_proj  = (const float*)d_in[1];
    const float* ln_g    = (const float*)d_in[2];
    const float* ln_b    = (const float*)d_in[3];
    const float* W_in    = (const float*)d_in[4];
    const float* W_out   = (const float*)d_in[5];
    const float* conv_k  = (const float*)d_in[6];
    float* out = (float*)d_out;

    float *ccx, *cb;
    __half *qkvh, *xin2, *xs2, *ao, *xp, *hp, *bx, *bh, *bproj, *bqkv, *bout;
    cudaGetSymbolAddress((void**)&ccx, g_ccx);
    cudaGetSymbolAddress((void**)&cb,  g_c);
    cudaGetSymbolAddress((void**)&qkvh, g_qkvh);
    cudaGetSymbolAddress((void**)&xin2, g_xin2);
    cudaGetSymbolAddress((void**)&xs2, g_xs2);
    cudaGetSymbolAddress((void**)&ao,  g_ao);
    cudaGetSymbolAddress((void**)&xp,  g_xp);
    cudaGetSymbolAddress((void**)&hp,  g_hp);
    cudaGetSymbolAddress((void**)&bx,  g_bx);
    cudaGetSymbolAddress((void**)&bh,  g_bh);
    cudaGetSymbolAddress((void**)&bproj, g_bproj);
    cudaGetSymbolAddress((void**)&bqkv, g_bqkv);
    cudaGetSymbolAddress((void**)&bout, g_bout);

    cudaFuncSetAttribute((void*)gemm_mma<1,256,4,5>, cudaFuncAttributeMaxDynamicSharedMemorySize, GEMM_SMEM);
    cudaFuncSetAttribute((void*)gemm_mma<1,256,2,6>, cudaFuncAttributeMaxDynamicSharedMemorySize, GEMM_SMEM);
    cudaFuncSetAttribute((void*)gemm_mma<1,128,2,2>, cudaFuncAttributeMaxDynamicSharedMemorySize, GEMM_SMEM);
    cudaFuncSetAttribute((void*)gemm_mma<9,128,18,0>, cudaFuncAttributeMaxDynamicSharedMemorySize, GEMM_SMEM);
    cudaFuncSetAttribute((void*)gemm_mma<9,128,18,1>, cudaFuncAttributeMaxDynamicSharedMemorySize, GEMM_SMEM);

    // side stream + events for conv_x / chain overlap (leaked; host-side only)
    cudaStream_t sA;
    cudaStreamCreate(&sA);
    cudaEvent_t evFork, evX[Sn];
    cudaEventCreateWithFlags(&evFork, cudaEventDisableTiming);
    for (int s = 0; s < Sn; s++)
        cudaEventCreateWithFlags(&evX[s], cudaEventDisableTiming);

    reorder_conv<<<(int)(((long)OC*1152 + 255)/256), 256>>>(conv_k, bx, bh);
    reorder_dense<<<(640*128+255)/256, 256>>>(W_proj, W_in, W_out, bproj, bqkv, bout);
    split_in<<<(int)(((long)TOK*64+255)/256), 256>>>(inputs, xin2);

    // proj + silu + LN fused (2-term), writes xs2 [hi|lo]
    gemm_mma<1,256,4,5><<<dim3(TOK/128, 1, 1), 512, GEMM_SMEM>>>(
        xin2, bproj, nullptr, 0, ln_g, ln_b, xs2, 1024L, 0L, 0L);

    // qkv = xln @ W_in (1-term, fp16 out)
    gemm_mma<1,256,2,6><<<dim3(TOK/128, 3, 1), 512, GEMM_SMEM>>>(
        xs2, bqkv, nullptr, 384, nullptr, nullptr, qkvh, 1024L, 0L, 0L);

    attn_core<<<Pn, 128>>>(qkvh, ao);

    // xres = ao @ W_out + inputs -> 1-term fp16 xp  (1-term ao, K'=128)
    gemm_mma<1,128,2,2><<<dim3(TOK/128, 1, 1), 512, GEMM_SMEM>>>(
        ao, bout, nullptr, 0, inputs, nullptr, xp, 1024L, 0L, 0L);

    // ---- fork: conv_x per-step slices in side stream, event after each ----
    cudaEventRecord(evFork, 0);
    cudaStreamWaitEvent(sA, evFork, 0);
    for (int z = 0; z < Sn; z++) {
        gemm_mma<9,128,18,0><<<dim3(Pn/128, 4, 1), 512, GEMM_SMEM, sA>>>(
            xp + (long)z*1024*128, bx, ccx + (long)z*Pn*OC, OC,
            nullptr, nullptr, nullptr, 16384L, 0L, 0L);
        cudaEventRecord(evX[z], sA);
    }

    // ---- main stream: sequential ConvLSTM chain, gated on conv_x slices ----
    for (int s = 0; s < Sn; s++) {
        cudaStreamWaitEvent(0, evX[s], 0);
        if (s > 0) {
            gemm_mma<9,128,18,1><<<dim3(Pn/128, 4, 1), 512, GEMM_SMEM>>>(
                hp, bh, ccx + (long)s*Pn*OC, OC, nullptr, nullptr, nullptr, 1024L, 0L, 0L);
        }
        gates_kernel<<<(Pn*En+255)/256, 256>>>(ccx + (long)s*Pn*OC, cb, hp, out, s, s == 0);
    }
}

// round 14
// speedup vs baseline: 1.6242x; 1.0807x over previous
#include <cuda_runtime.h>
#include <cuda_fp16.h>
#include <cstdint>

// Problem constants
#define Bn 8
#define Sn 16
#define En 128
#define TOK (Bn*Sn*32*32)      // 131072
#define Pn (Bn*32*32)          // 8192
#define OC 512

// -------- scratch (device globals) --------
__device__ float g_ccx[(long)TOK*OC];         // fp32 gate pre-activations
__device__ float g_c[Pn*En];
__device__ __half g_qkvh[(long)TOK*384];
__device__ __half g_xin2[(long)TOK*256];
__device__ __half g_xs2[(long)TOK*256];
__device__ __half g_ao[(long)TOK*128];        // 1-term attention out
__device__ __half g_xp[(long)TOK*128];
__device__ __half g_hp[Pn*128];
__device__ __half g_bx[(long)OC*1152];
__device__ __half g_bh[(long)OC*1152];
__device__ __half g_bproj[128*256];
__device__ __half g_bqkv[384*256];
__device__ __half g_bout[128*128];            // 1-term out-proj weights

// ==================== helpers ====================
__device__ __forceinline__ uint32_t smem_u32(const void* p) {
    uint32_t a;
    asm("{ .reg .u64 t; cvta.to.shared.u64 t, %1; cvt.u32.u64 %0, t; }" : "=r"(a) : "l"(p));
    return a;
}
__device__ __forceinline__ void cp16(uint32_t dst, const void* src, bool pred) {
    asm volatile("cp.async.cg.shared.global [%0], [%1], 16, %2;"
        :: "r"(dst), "l"(src), "r"(pred ? 16u : 0u));
}
#define CP_COMMIT() asm volatile("cp.async.commit_group;" ::: "memory")
#define CP_WAIT3()  asm volatile("cp.async.wait_group 3;" ::: "memory")
#define CP_WAIT2()  asm volatile("cp.async.wait_group 2;" ::: "memory")

__device__ __forceinline__ void ldm_x4(uint32_t* r, uint32_t addr) {
    asm volatile("ldmatrix.sync.aligned.m8n8.x4.shared.b16 {%0,%1,%2,%3}, [%4];"
        : "=r"(r[0]), "=r"(r[1]), "=r"(r[2]), "=r"(r[3]) : "r"(addr));
}
__device__ __forceinline__ void mma16816(float* d, const uint32_t* a, uint32_t b0, uint32_t b1) {
    asm volatile("mma.sync.aligned.m16n8k16.row.col.f32.f16.f16.f32 "
        "{%0,%1,%2,%3}, {%4,%5,%6,%7}, {%8,%9}, {%0,%1,%2,%3};"
        : "+f"(d[0]), "+f"(d[1]), "+f"(d[2]), "+f"(d[3])
        : "r"(a[0]), "r"(a[1]), "r"(a[2]), "r"(a[3]), "r"(b0), "r"(b1));
}
__device__ __forceinline__ void split_h(float x, __half& hi, __half& lo) {
    hi = __float2half(x);
    lo = __float2half(x - __half2float(hi));
}

// -------------------- small kernels --------------------
__global__ void split_in(const float* __restrict__ inp, __half* __restrict__ x2) {
    long idx = (long)blockIdx.x*blockDim.x + threadIdx.x;
    if (idx >= (long)TOK*64) return;
    long row = idx >> 6; int e2 = idx & 63;
    float2 v = ((const float2*)inp)[idx];
    __half h0, l0, h1, l1;
    split_h(v.x, h0, l0);
    split_h(v.y, h1, l1);
    ((__half2*)(x2 + row*256))[e2]      = __halves2half2(h0, h1);
    ((__half2*)(x2 + row*256 + 128))[e2] = __halves2half2(l0, l1);
}
__global__ void reorder_conv(const float* __restrict__ ck,
                             __half* __restrict__ bx, __half* __restrict__ bh) {
    long idx = (long)blockIdx.x*blockDim.x + threadIdx.x;
    if (idx >= (long)OC*1152) return;
    int oc = idx / 1152, k = idx % 1152;
    int tap = k >> 7, ic = k & 127;
    int ky = tap / 3, kx = tap % 3;
    bx[idx] = __float2half(ck[(((long)oc*256 + ic      )*3 + ky)*3 + kx]);
    bh[idx] = __float2half(ck[(((long)oc*256 + 128 + ic)*3 + ky)*3 + kx]);
}
__global__ void reorder_dense(const float* __restrict__ wp, const float* __restrict__ wi,
                              const float* __restrict__ wo,
                              __half* __restrict__ bp, __half* __restrict__ bi,
                              __half* __restrict__ bo) {
    int idx = blockIdx.x*blockDim.x + threadIdx.x;
    if (idx >= 640*128) return;
    int n = idx >> 7, k = idx & 127;
    if (n < 128) {                       // proj: 2-term [w|w]
        __half v = __float2half(wp[k*128 + n]);
        bp[n*256 + k]       = v;
        bp[n*256 + 128 + k] = v;
    } else if (n < 512) {                // qkv: 2-term [w|w]
        int nn = n - 128;
        __half v = __float2half(wi[k*384 + nn]);
        bi[nn*256 + k]       = v;
        bi[nn*256 + 128 + k] = v;
    } else {                             // out: 1-term
        int nn = n - 512;
        bo[nn*128 + k] = __float2half(wo[k*128 + nn]);
    }
}

// -------------------- attention core (fp16 qkv in, 1-term ao out) --------------------
__global__ __launch_bounds__(128)
void attn_core(const __half* __restrict__ qkv, __half* __restrict__ ao) {
    __shared__ float qs[16][384];
    int bid = blockIdx.x;
    int b = bid >> 10, hw = bid & 1023;
    int tid = threadIdx.x;
    for (int idx = tid; idx < 16*192; idx += 128) {
        int t = idx / 192, f = idx % 192;
        __half2 h2 = ((const __half2*)(qkv + ((long)(b*16+t)*1024 + hw)*384))[f];
        float2 f2 = __half22float2(h2);
        qs[t][2*f]   = f2.x;
        qs[t][2*f+1] = f2.y;
    }
    __syncthreads();
    int i = tid >> 4, srow = tid & 15;
    float qd[16];
    #pragma unroll
    for (int d=0; d<16; d++) qd[d] = qs[srow][i*48+d];
    float sc[16];
    float mx = -1e30f;
    #pragma unroll
    for (int l=0;l<16;l++) {
        float sv = 0.f;
        #pragma unroll
        for (int d=0;d<16;d++) sv += qd[d]*qs[l][i*48+16+d];
        sv = sv*0.25f + (l<=srow ? 1.0f : -1000.0f);
        sc[l]=sv; mx = fmaxf(mx, sv);
    }
    float sum=0.f;
    #pragma unroll
    for (int l=0;l<16;l++){ sc[l]=__expf(sc[l]-mx); sum+=sc[l]; }
    float inv = 1.0f/sum;
    float o[16];
    #pragma unroll
    for (int d=0;d<16;d++) o[d]=0.f;
    #pragma unroll
    for (int l=0;l<16;l++) {
        float wl = sc[l]*inv;
        #pragma unroll
        for (int d=0;d<16;d++) o[d] += wl*qs[l][i*48+32+d];
    }
    long t = (long)(b*16+srow)*1024 + hw;
    #pragma unroll
    for (int d=0;d<16;d+=2)
        ((__half2*)(ao + t*128 + i*16))[d>>1] =
            __halves2half2(__float2half(o[d]), __float2half(o[d+1]));
}

// -------------------- universal warp-MMA fp16 GEMM / implicit conv --------------------
#define ROWB 144
#define STAGE_A (128*ROWB)
#define STAGE   (2*STAGE_A)
#define NSTAGE  4
#define GEMM_SMEM (NSTAGE*STAGE)  // 147456
#define SREDW 132

template<int NTAP, int ALEN, int NCH, int EPI>
__global__ __launch_bounds__(512, 1)
void gemm_mma(const __half* __restrict__ A, const __half* __restrict__ Bw,
              float* __restrict__ Out, int ldo,
              const float* __restrict__ aux, const float* __restrict__ aux2,
              __half* __restrict__ outh,
              long a_bstride, long a_zstride, long o_zstride) {
    constexpr int CPT = ALEN / 64;
    extern __shared__ char smem[];
    uint32_t sb = smem_u32(smem);

    int tid = threadIdx.x;
    int m0 = blockIdx.x * 128;
    int n0 = blockIdx.y * 128;
    int z  = blockIdx.z;

    int lrow = tid >> 2;
    int lseg = (tid & 3) * 2;
    int p = m0 + lrow;
    int bb = p >> 10, pix = p & 1023;
    int y = pix >> 5, x = pix & 31;
    long arow_base = (long)bb * a_bstride + (long)z * a_zstride;

    auto load_chunk = [&](int c, int st) {
        int koff = (c % CPT) * 64;
        bool v = true;
        long arow;
        if (NTAP == 9) {
            int tap = c / CPT;
            int ky = tap/3 - 1, kx = tap%3 - 1;
            int yy = y + ky, xx = x + kx;
            v = ((unsigned)yy < 32u) && ((unsigned)xx < 32u);
            arow = arow_base + ((yy<<5) + xx);
        } else {
            arow = arow_base + pix;
        }
        const __half* asrc = v ? (A + arow*ALEN + koff + lseg*8) : A;
        uint32_t ab = sb + st*STAGE + lrow*ROWB + lseg*16;
        cp16(ab,      asrc,     v);
        cp16(ab + 16, asrc + 8, v);
        const __half* bsrc = Bw + (long)(n0 + lrow)*(NTAP*ALEN) + c*64 + lseg*8;
        uint32_t bbs = sb + st*STAGE + STAGE_A + lrow*ROWB + lseg*16;
        cp16(bbs,      bsrc,     true);
        cp16(bbs + 16, bsrc + 8, true);
        CP_COMMIT();
    };

    int w = tid >> 5, l = tid & 31;
    int m_off = (w >> 2) * 32;
    int n_off = (w & 3) * 32;
    int lr = l & 15, lh = (l >> 4) << 4;

    float acc[2][4][4];
    #pragma unroll
    for (int i=0;i<2;i++)
        #pragma unroll
        for (int j=0;j<4;j++)
            #pragma unroll
            for (int q=0;q<4;q++) acc[i][j][q]=0.f;

    load_chunk(0, 0);
    if (NCH > 1) load_chunk(1, 1); else CP_COMMIT();
    if (NCH > 2) load_chunk(2, 2); else CP_COMMIT();

    for (int c = 0; c < NCH; c++) {
        int st = c & (NSTAGE-1);
        if (c + 3 < NCH) load_chunk(c + 3, (c + 3) & (NSTAGE-1));
        else CP_COMMIT();
        CP_WAIT3();
        __syncthreads();

        uint32_t a_st = sb + st*STAGE;
        uint32_t b_st = a_st + STAGE_A;
        #pragma unroll
        for (int ks = 0; ks < 4; ks++) {
            uint32_t af[2][4], bf[2][4];
            #pragma unroll
            for (int mt = 0; mt < 2; mt++)
                ldm_x4(af[mt], a_st + (m_off + mt*16 + lr)*ROWB + ks*32 + lh);
            #pragma unroll
            for (int nt = 0; nt < 2; nt++)
                ldm_x4(bf[nt], b_st + (n_off + nt*16 + lr)*ROWB + ks*32 + lh);
            #pragma unroll
            for (int mt = 0; mt < 2; mt++) {
                #pragma unroll
                for (int n8 = 0; n8 < 4; n8++) {
                    int nt = n8 >> 1, hi = n8 & 1;
                    mma16816(acc[mt][n8], af[mt], bf[nt][hi], bf[nt][2+hi]);
                }
            }
        }
        __syncthreads();
    }

    if (EPI == 5) {
        float* sred = (float*)smem;
        #pragma unroll
        for (int mt = 0; mt < 2; mt++) {
            int r0 = m_off + mt*16 + (l >> 2);
            #pragma unroll
            for (int n8 = 0; n8 < 4; n8++) {
                int cc = n_off + n8*8 + (l & 3)*2;
                #pragma unroll
                for (int q = 0; q < 4; q++) {
                    float v = acc[mt][n8][q];
                    v = v / (1.0f + __expf(-v));
                    sred[(r0 + (q>>1)*8)*SREDW + cc + (q&1)] = v;
                }
            }
        }
        __syncthreads();
        #pragma unroll
        for (int rr = 0; rr < 8; rr++) {
            int row = w*8 + rr;
            float v4[4];
            float s = 0.f, qs = 0.f;
            #pragma unroll
            for (int j = 0; j < 4; j++) {
                float v = sred[row*SREDW + l + j*32];
                v4[j] = v; s += v; qs += v*v;
            }
            #pragma unroll
            for (int off = 16; off; off >>= 1) {
                s  += __shfl_xor_sync(0xffffffff, s, off);
                qs += __shfl_xor_sync(0xffffffff, qs, off);
            }
            float mu = s * (1.0f/128.0f);
            float rs = rsqrtf(qs * (1.0f/128.0f) - mu*mu + 1e-5f);
            long grow = m0 + row;
            #pragma unroll
            for (int j = 0; j < 4; j++) {
                int e = l + j*32;
                float v = (v4[j] - mu) * rs * aux[e] + aux2[e];
                __half hi, lo;
                split_h(v, hi, lo);
                outh[grow*256 + e]       = hi;
                outh[grow*256 + 128 + e] = lo;
            }
        }
        return;
    }

    #pragma unroll
    for (int mt = 0; mt < 2; mt++) {
        int r0 = m0 + m_off + mt*16 + (l >> 2);
        #pragma unroll
        for (int n8 = 0; n8 < 4; n8++) {
            int cc = n0 + n_off + n8*8 + (l & 3)*2;
            float d0 = acc[mt][n8][0], d1 = acc[mt][n8][1];
            float d2 = acc[mt][n8][2], d3 = acc[mt][n8][3];
            if (EPI == 2) {
                float v0 = d0 + aux[(long)r0*128 + cc];
                float v1 = d1 + aux[(long)r0*128 + cc + 1];
                float v2 = d2 + aux[(long)(r0+8)*128 + cc];
                float v3 = d3 + aux[(long)(r0+8)*128 + cc + 1];
                outh[(long)r0*128 + cc]         = __float2half(v0);
                outh[(long)r0*128 + cc + 1]     = __float2half(v1);
                outh[(long)(r0+8)*128 + cc]     = __float2half(v2);
                outh[(long)(r0+8)*128 + cc + 1] = __float2half(v3);
            } else if (EPI == 6) {
                __half* q0 = outh + (long)r0*ldo + cc;
                __half* q1 = outh + (long)(r0+8)*ldo + cc;
                q0[0] = __float2half(d0); q0[1] = __float2half(d1);
                q1[0] = __float2half(d2); q1[1] = __float2half(d3);
            } else {
                float* p0 = Out + ((long)z*o_zstride + r0    )*ldo + cc;
                float* p1 = Out + ((long)z*o_zstride + r0 + 8)*ldo + cc;
                if (EPI == 1) { d0 += p0[0]; d1 += p0[1]; d2 += p1[0]; d3 += p1[1]; }
                p0[0] = d0; p0[1] = d1;
                p1[0] = d2; p1[1] = d3;
            }
        }
    }
}

// -------------------- conv_h: single-wave 128x256 tiles, 512 thr, 3 stages --------------------
#define H2_A (128*ROWB)            // 18432
#define H2_B (256*ROWB)            // 36864
#define H2_STAGE (H2_A + H2_B)     // 55296
#define H2_SMEM (3*H2_STAGE)       // 165888

__global__ __launch_bounds__(512, 1)
void convh2_mma(const __half* __restrict__ A, const __half* __restrict__ Bw,
                float* __restrict__ Out) {
    extern __shared__ char smem[];
    uint32_t sb = smem_u32(smem);
    int tid = threadIdx.x;
    int m0 = blockIdx.x * 128;
    int n0 = blockIdx.y * 256;

    auto load_chunk = [&](int c, int st) {
        int tap  = c >> 1;
        int koff = (c & 1) * 64;
        int ky = tap/3 - 1, kx = tap%3 - 1;
        uint32_t a_st = sb + st*H2_STAGE;
        uint32_t b_st = a_st + H2_A;
        // A: 128 rows x 8 segs = 1024 units, 2 per thread
        #pragma unroll
        for (int i = 0; i < 2; i++) {
            int id = tid + i*512;
            int row = id >> 3, seg = id & 7;
            int p = m0 + row;
            int y = (p >> 5) & 31, x = p & 31;
            int yy = y + ky, xx = x + kx;
            bool v = ((unsigned)yy < 32u) && ((unsigned)xx < 32u);
            const __half* asrc = v
                ? (A + ((long)(p >> 10)*1024 + (yy<<5) + xx)*128 + koff + seg*8)
                : A;
            cp16(a_st + row*ROWB + seg*16, asrc, v);
        }
        // B: 256 rows x 8 segs = 2048 units, 4 per thread
        #pragma unroll
        for (int i = 0; i < 4; i++) {
            int id = tid + i*512;
            int row = id >> 3, seg = id & 7;
            const __half* bsrc = Bw + (long)(n0 + row)*1152 + c*64 + seg*8;
            cp16(b_st + row*ROWB + seg*16, bsrc, true);
        }
        CP_COMMIT();
    };

    int w = tid >> 5, l = tid & 31;
    int m_off = (w >> 2) * 32;
    int n_off = (w & 3) * 64;
    int lr = l & 15, lh = (l >> 4) << 4;

    float acc[2][8][4];
    #pragma unroll
    for (int i=0;i<2;i++)
        #pragma unroll
        for (int j=0;j<8;j++)
            #pragma unroll
            for (int q=0;q<4;q++) acc[i][j][q]=0.f;

    load_chunk(0, 0);
    load_chunk(1, 1);

    for (int c = 0; c < 18; c++) {
        int st = c % 3;
        if (c + 2 < 18) load_chunk(c + 2, (c + 2) % 3);
        else CP_COMMIT();
        CP_WAIT2();
        __syncthreads();

        uint32_t a_st = sb + st*H2_STAGE;
        uint32_t b_st = a_st + H2_A;
        #pragma unroll
        for (int ks = 0; ks < 4; ks++) {
            uint32_t af[2][4], bf[4][4];
            #pragma unroll
            for (int mt = 0; mt < 2; mt++)
                ldm_x4(af[mt], a_st + (m_off + mt*16 + lr)*ROWB + ks*32 + lh);
            #pragma unroll
            for (int nt = 0; nt < 4; nt++)
                ldm_x4(bf[nt], b_st + (n_off + nt*16 + lr)*ROWB + ks*32 + lh);
            #pragma unroll
            for (int mt = 0; mt < 2; mt++) {
                #pragma unroll
                for (int n8 = 0; n8 < 8; n8++) {
                    int nt = n8 >> 1, hi = n8 & 1;
                    mma16816(acc[mt][n8], af[mt], bf[nt][hi], bf[nt][2+hi]);
                }
            }
        }
        __syncthreads();
    }

    #pragma unroll
    for (int mt = 0; mt < 2; mt++) {
        int r0 = m0 + m_off + mt*16 + (l >> 2);
        #pragma unroll
        for (int n8 = 0; n8 < 8; n8++) {
            int cc = n0 + n_off + n8*8 + (l & 3)*2;
            float* p0 = Out + (long)r0*OC + cc;
            float* p1 = Out + (long)(r0+8)*OC + cc;
            p0[0] += acc[mt][n8][0]; p0[1] += acc[mt][n8][1];
            p1[0] += acc[mt][n8][2]; p1[1] += acc[mt][n8][3];
        }
    }
}

// -------------------- LSTM gates --------------------
__global__ void gates_kernel(const float* __restrict__ cc,
                             float* __restrict__ cbuf,
                             __half* __restrict__ hp,
                             float* __restrict__ out, int s, int czero) {
    int idx = blockIdx.x*blockDim.x + threadIdx.x;
    if (idx >= Pn*En) return;
    int p = idx >> 7, e = idx & 127;
    const float* row = cc + (long)p*OC;
    float ci = row[e], cf = row[128+e], co = row[256+e], cg = row[384+e];
    float si = 1.f/(1.f+__expf(-ci));
    float sf = 1.f/(1.f+__expf(-cf));
    float so = 1.f/(1.f+__expf(-co));
    float c_prev = czero ? 0.f : cbuf[idx];
    float c_next = sf*c_prev + si*tanhf(cg);
    float h_next = so*tanhf(c_next);
    cbuf[idx] = c_next;
    hp[(long)p*128 + e] = __float2half(h_next);
    int b = p >> 10, pix = p & 1023;
    out[((long)(b*16+s)*1024 + pix)*128 + e] = h_next;
}

// -------------------- launch --------------------
extern "C" void kernel_launch(void* const* d_in, const int* in_sizes, int n_in,
                              void* d_out, int out_size) {
    const float* inputs  = (const float*)d_in[0];
    const float* W_proj  = (const float*)d_in[1];
    const float* ln_g    = (const float*)d_in[2];
    const float* ln_b    = (const float*)d_in[3];
    const float* W_in    = (const float*)d_in[4];
    const float* W_out   = (const float*)d_in[5];
    const float* conv_k  = (const float*)d_in[6];
    float* out = (float*)d_out;

    float *ccx, *cb;
    __half *qkvh, *xin2, *xs2, *ao, *xp, *hp, *bx, *bh, *bproj, *bqkv, *bout;
    cudaGetSymbolAddress((void**)&ccx, g_ccx);
    cudaGetSymbolAddress((void**)&cb,  g_c);
    cudaGetSymbolAddress((void**)&qkvh, g_qkvh);
    cudaGetSymbolAddress((void**)&xin2, g_xin2);
    cudaGetSymbolAddress((void**)&xs2, g_xs2);
    cudaGetSymbolAddress((void**)&ao,  g_ao);
    cudaGetSymbolAddress((void**)&xp,  g_xp);
    cudaGetSymbolAddress((void**)&hp,  g_hp);
    cudaGetSymbolAddress((void**)&bx,  g_bx);
    cudaGetSymbolAddress((void**)&bh,  g_bh);
    cudaGetSymbolAddress((void**)&bproj, g_bproj);
    cudaGetSymbolAddress((void**)&bqkv, g_bqkv);
    cudaGetSymbolAddress((void**)&bout, g_bout);

    cudaFuncSetAttribute((void*)gemm_mma<1,256,4,5>, cudaFuncAttributeMaxDynamicSharedMemorySize, GEMM_SMEM);
    cudaFuncSetAttribute((void*)gemm_mma<1,256,2,6>, cudaFuncAttributeMaxDynamicSharedMemorySize, GEMM_SMEM);
    cudaFuncSetAttribute((void*)gemm_mma<1,128,2,2>, cudaFuncAttributeMaxDynamicSharedMemorySize, GEMM_SMEM);
    cudaFuncSetAttribute((void*)gemm_mma<9,128,18,0>, cudaFuncAttributeMaxDynamicSharedMemorySize, GEMM_SMEM);
    cudaFuncSetAttribute((void*)convh2_mma, cudaFuncAttributeMaxDynamicSharedMemorySize, H2_SMEM);

    // side stream + events (host-side only)
    cudaStream_t sA;
    cudaStreamCreate(&sA);
    cudaEvent_t evFork, evX[Sn];
    cudaEventCreateWithFlags(&evFork, cudaEventDisableTiming);
    for (int s = 0; s < Sn; s++)
        cudaEventCreateWithFlags(&evX[s], cudaEventDisableTiming);

    // conv weight reorder overlaps the dense section on the side stream
    reorder_conv<<<(int)(((long)OC*1152 + 255)/256), 256, 0, sA>>>(conv_k, bx, bh);

    reorder_dense<<<(640*128+255)/256, 256>>>(W_proj, W_in, W_out, bproj, bqkv, bout);
    split_in<<<(int)(((long)TOK*64+255)/256), 256>>>(inputs, xin2);

    // proj + silu + LN fused (2-term), writes xs2 [hi|lo]
    gemm_mma<1,256,4,5><<<dim3(TOK/128, 1, 1), 512, GEMM_SMEM>>>(
        xin2, bproj, nullptr, 0, ln_g, ln_b, xs2, 1024L, 0L, 0L);

    // qkv = xln @ W_in (2-term in, fp16 out)
    gemm_mma<1,256,2,6><<<dim3(TOK/128, 3, 1), 512, GEMM_SMEM>>>(
        xs2, bqkv, nullptr, 384, nullptr, nullptr, qkvh, 1024L, 0L, 0L);

    attn_core<<<Pn, 128>>>(qkvh, ao);

    // xres = ao @ W_out + inputs -> 1-term fp16 xp
    gemm_mma<1,128,2,2><<<dim3(TOK/128, 1, 1), 512, GEMM_SMEM>>>(
        ao, bout, nullptr, 0, inputs, nullptr, xp, 1024L, 0L, 0L);

    // ---- fork: conv_x per-step slices on side stream (after xp ready) ----
    cudaEventRecord(evFork, 0);
    cudaStreamWaitEvent(sA, evFork, 0);
    for (int z = 0; z < Sn; z++) {
        gemm_mma<9,128,18,0><<<dim3(Pn/128, 4, 1), 512, GEMM_SMEM, sA>>>(
            xp + (long)z*1024*128, bx, ccx + (long)z*Pn*OC, OC,
            nullptr, nullptr, nullptr, 16384L, 0L, 0L);
        cudaEventRecord(evX[z], sA);
    }

    // ---- main stream: sequential ConvLSTM chain ----
    for (int s = 0; s < Sn; s++) {
        cudaStreamWaitEvent(0, evX[s], 0);
        if (s > 0) {
            convh2_mma<<<dim3(Pn/128, 2, 1), 512, H2_SMEM>>>(
                hp, bh, ccx + (long)s*Pn*OC);
        }
        gates_kernel<<<(Pn*En+255)/256, 256>>>(ccx + (long)s*Pn*OC, cb, hp, out, s, s == 0);
    }
}

// round 16
// speedup vs baseline: 1.6294x; 1.0032x over previous
#include <cuda_runtime.h>
#include <cuda_fp16.h>
#include <cstdint>

// Problem constants
#define Bn 8
#define Sn 16
#define En 128
#define TOK (Bn*Sn*32*32)      // 131072
#define Pn (Bn*32*32)          // 8192
#define OC 512

// -------- scratch (device globals) --------
__device__ float g_ccx[(long)TOK*OC];         // fp32 gate pre-activations
__device__ float g_c[Pn*En];
__device__ __half g_qkvh[(long)TOK*384];
__device__ __half g_xin2[(long)TOK*256];
__device__ __half g_xs2[(long)TOK*256];
__device__ __half g_ao[(long)TOK*128];        // 1-term attention out
__device__ __half g_xp[(long)TOK*128];
__device__ __half g_hp[Pn*128];
__device__ __half g_bx[(long)OC*1152];
__device__ __half g_bh[(long)OC*1152];
__device__ __half g_bproj[128*256];
__device__ __half g_bqkv[384*256];
__device__ __half g_bout[128*128];            // 1-term out-proj weights

// ==================== helpers ====================
__device__ __forceinline__ uint32_t smem_u32(const void* p) {
    uint32_t a;
    asm("{ .reg .u64 t; cvta.to.shared.u64 t, %1; cvt.u32.u64 %0, t; }" : "=r"(a) : "l"(p));
    return a;
}
__device__ __forceinline__ void cp16(uint32_t dst, const void* src, bool pred) {
    asm volatile("cp.async.cg.shared.global [%0], [%1], 16, %2;"
        :: "r"(dst), "l"(src), "r"(pred ? 16u : 0u));
}
#define CP_COMMIT() asm volatile("cp.async.commit_group;" ::: "memory")
#define CP_WAIT3()  asm volatile("cp.async.wait_group 3;" ::: "memory")
#define CP_WAIT2()  asm volatile("cp.async.wait_group 2;" ::: "memory")

__device__ __forceinline__ void ldm_x4(uint32_t* r, uint32_t addr) {
    asm volatile("ldmatrix.sync.aligned.m8n8.x4.shared.b16 {%0,%1,%2,%3}, [%4];"
        : "=r"(r[0]), "=r"(r[1]), "=r"(r[2]), "=r"(r[3]) : "r"(addr));
}
__device__ __forceinline__ void mma16816(float* d, const uint32_t* a, uint32_t b0, uint32_t b1) {
    asm volatile("mma.sync.aligned.m16n8k16.row.col.f32.f16.f16.f32 "
        "{%0,%1,%2,%3}, {%4,%5,%6,%7}, {%8,%9}, {%0,%1,%2,%3};"
        : "+f"(d[0]), "+f"(d[1]), "+f"(d[2]), "+f"(d[3])
        : "r"(a[0]), "r"(a[1]), "r"(a[2]), "r"(a[3]), "r"(b0), "r"(b1));
}
__device__ __forceinline__ void split_h(float x, __half& hi, __half& lo) {
    hi = __float2half(x);
    lo = __float2half(x - __half2float(hi));
}

// -------------------- small kernels --------------------
__global__ void split_in(const float* __restrict__ inp, __half* __restrict__ x2) {
    long idx = (long)blockIdx.x*blockDim.x + threadIdx.x;
    if (idx >= (long)TOK*64) return;
    long row = idx >> 6; int e2 = idx & 63;
    float2 v = ((const float2*)inp)[idx];
    __half h0, l0, h1, l1;
    split_h(v.x, h0, l0);
    split_h(v.y, h1, l1);
    ((__half2*)(x2 + row*256))[e2]      = __halves2half2(h0, h1);
    ((__half2*)(x2 + row*256 + 128))[e2] = __halves2half2(l0, l1);
}
__global__ void reorder_conv(const float* __restrict__ ck,
                             __half* __restrict__ bx, __half* __restrict__ bh) {
    long idx = (long)blockIdx.x*blockDim.x + threadIdx.x;
    if (idx >= (long)OC*1152) return;
    int oc = idx / 1152, k = idx % 1152;
    int tap = k >> 7, ic = k & 127;
    int ky = tap / 3, kx = tap % 3;
    bx[idx] = __float2half(ck[(((long)oc*256 + ic      )*3 + ky)*3 + kx]);
    bh[idx] = __float2half(ck[(((long)oc*256 + 128 + ic)*3 + ky)*3 + kx]);
}
__global__ void reorder_dense(const float* __restrict__ wp, const float* __restrict__ wi,
                              const float* __restrict__ wo,
                              __half* __restrict__ bp, __half* __restrict__ bi,
                              __half* __restrict__ bo) {
    int idx = blockIdx.x*blockDim.x + threadIdx.x;
    if (idx >= 640*128) return;
    int n = idx >> 7, k = idx & 127;
    if (n < 128) {
        __half v = __float2half(wp[k*128 + n]);
        bp[n*256 + k]       = v;
        bp[n*256 + 128 + k] = v;
    } else if (n < 512) {
        int nn = n - 128;
        __half v = __float2half(wi[k*384 + nn]);
        bi[nn*256 + k]       = v;
        bi[nn*256 + 128 + k] = v;
    } else {
        int nn = n - 512;
        bo[nn*128 + k] = __float2half(wo[k*128 + nn]);
    }
}

// -------------------- attention core: 256 thr, 2 positions per CTA --------------------
__global__ __launch_bounds__(256)
void attn_core(const __half* __restrict__ qkv, __half* __restrict__ ao) {
    __shared__ float qs[2][16][384];
    int tid = threadIdx.x;
    int pos = tid >> 7, wt = tid & 127;
    int gp = blockIdx.x*2 + pos;           // global (b,hw) position
    int b = gp >> 10, hw = gp & 1023;
    for (int idx = wt; idx < 16*192; idx += 128) {
        int t = idx / 192, f = idx % 192;
        __half2 h2 = ((const __half2*)(qkv + ((long)(b*16+t)*1024 + hw)*384))[f];
        float2 f2 = __half22float2(h2);
        qs[pos][t][2*f]   = f2.x;
        qs[pos][t][2*f+1] = f2.y;
    }
    __syncthreads();
    int i = wt >> 4, srow = wt & 15;
    float qd[16];
    #pragma unroll
    for (int d=0; d<16; d++) qd[d] = qs[pos][srow][i*48+d];
    float sc[16];
    float mx = -1e30f;
    #pragma unroll
    for (int l=0;l<16;l++) {
        float sv = 0.f;
        #pragma unroll
        for (int d=0;d<16;d++) sv += qd[d]*qs[pos][l][i*48+16+d];
        sv = sv*0.25f + (l<=srow ? 1.0f : -1000.0f);
        sc[l]=sv; mx = fmaxf(mx, sv);
    }
    float sum=0.f;
    #pragma unroll
    for (int l=0;l<16;l++){ sc[l]=__expf(sc[l]-mx); sum+=sc[l]; }
    float inv = 1.0f/sum;
    float o[16];
    #pragma unroll
    for (int d=0;d<16;d++) o[d]=0.f;
    #pragma unroll
    for (int l=0;l<16;l++) {
        float wl = sc[l]*inv;
        #pragma unroll
        for (int d=0;d<16;d++) o[d] += wl*qs[pos][l][i*48+32+d];
    }
    long t = (long)(b*16+srow)*1024 + hw;
    #pragma unroll
    for (int d=0;d<16;d+=2)
        ((__half2*)(ao + t*128 + i*16))[d>>1] =
            __halves2half2(__float2half(o[d]), __float2half(o[d+1]));
}

// -------------------- universal warp-MMA fp16 GEMM / implicit conv --------------------
#define ROWB 144
#define STAGE_A (128*ROWB)
#define STAGE   (2*STAGE_A)
#define NSTAGE  4
#define GEMM_SMEM (NSTAGE*STAGE)  // 147456
#define SREDW 132

template<int NTAP, int ALEN, int NCH, int EPI>
__global__ __launch_bounds__(512, 1)
void gemm_mma(const __half* __restrict__ A, const __half* __restrict__ Bw,
              float* __restrict__ Out, int ldo,
              const float* __restrict__ aux, const float* __restrict__ aux2,
              __half* __restrict__ outh,
              long a_bstride, long a_zstride, long o_zstride) {
    constexpr int CPT = ALEN / 64;
    extern __shared__ char smem[];
    uint32_t sb = smem_u32(smem);

    int tid = threadIdx.x;
    int m0 = blockIdx.x * 128;
    int n0 = blockIdx.y * 128;
    int z  = blockIdx.z;

    int lrow = tid >> 2;
    int lseg = (tid & 3) * 2;
    int p = m0 + lrow;
    int bb = p >> 10, pix = p & 1023;
    int y = pix >> 5, x = pix & 31;
    long arow_base = (long)bb * a_bstride + (long)z * a_zstride;

    auto load_chunk = [&](int c, int st) {
        int koff = (c % CPT) * 64;
        bool v = true;
        long arow;
        if (NTAP == 9) {
            int tap = c / CPT;
            int ky = tap/3 - 1, kx = tap%3 - 1;
            int yy = y + ky, xx = x + kx;
            v = ((unsigned)yy < 32u) && ((unsigned)xx < 32u);
            arow = arow_base + ((yy<<5) + xx);
        } else {
            arow = arow_base + pix;
        }
        const __half* asrc = v ? (A + arow*ALEN + koff + lseg*8) : A;
        uint32_t ab = sb + st*STAGE + lrow*ROWB + lseg*16;
        cp16(ab,      asrc,     v);
        cp16(ab + 16, asrc + 8, v);
        const __half* bsrc = Bw + (long)(n0 + lrow)*(NTAP*ALEN) + c*64 + lseg*8;
        uint32_t bbs = sb + st*STAGE + STAGE_A + lrow*ROWB + lseg*16;
        cp16(bbs,      bsrc,     true);
        cp16(bbs + 16, bsrc + 8, true);
        CP_COMMIT();
    };

    int w = tid >> 5, l = tid & 31;
    int m_off = (w >> 2) * 32;
    int n_off = (w & 3) * 32;
    int lr = l & 15, lh = (l >> 4) << 4;

    float acc[2][4][4];
    #pragma unroll
    for (int i=0;i<2;i++)
        #pragma unroll
        for (int j=0;j<4;j++)
            #pragma unroll
            for (int q=0;q<4;q++) acc[i][j][q]=0.f;

    load_chunk(0, 0);
    if (NCH > 1) load_chunk(1, 1); else CP_COMMIT();
    if (NCH > 2) load_chunk(2, 2); else CP_COMMIT();

    for (int c = 0; c < NCH; c++) {
        int st = c & (NSTAGE-1);
        if (c + 3 < NCH) load_chunk(c + 3, (c + 3) & (NSTAGE-1));
        else CP_COMMIT();
        CP_WAIT3();
        __syncthreads();

        uint32_t a_st = sb + st*STAGE;
        uint32_t b_st = a_st + STAGE_A;
        #pragma unroll
        for (int ks = 0; ks < 4; ks++) {
            uint32_t af[2][4], bf[2][4];
            #pragma unroll
            for (int mt = 0; mt < 2; mt++)
                ldm_x4(af[mt], a_st + (m_off + mt*16 + lr)*ROWB + ks*32 + lh);
            #pragma unroll
            for (int nt = 0; nt < 2; nt++)
                ldm_x4(bf[nt], b_st + (n_off + nt*16 + lr)*ROWB + ks*32 + lh);
            #pragma unroll
            for (int mt = 0; mt < 2; mt++) {
                #pragma unroll
                for (int n8 = 0; n8 < 4; n8++) {
                    int nt = n8 >> 1, hi = n8 & 1;
                    mma16816(acc[mt][n8], af[mt], bf[nt][hi], bf[nt][2+hi]);
                }
            }
        }
        __syncthreads();
    }

    if (EPI == 5) {
        float* sred = (float*)smem;
        #pragma unroll
        for (int mt = 0; mt < 2; mt++) {
            int r0 = m_off + mt*16 + (l >> 2);
            #pragma unroll
            for (int n8 = 0; n8 < 4; n8++) {
                int cc = n_off + n8*8 + (l & 3)*2;
                #pragma unroll
                for (int q = 0; q < 4; q++) {
                    float v = acc[mt][n8][q];
                    v = v / (1.0f + __expf(-v));
                    sred[(r0 + (q>>1)*8)*SREDW + cc + (q&1)] = v;
                }
            }
        }
        __syncthreads();
        #pragma unroll
        for (int rr = 0; rr < 8; rr++) {
            int row = w*8 + rr;
            float v4[4];
            float s = 0.f, qs = 0.f;
            #pragma unroll
            for (int j = 0; j < 4; j++) {
                float v = sred[row*SREDW + l + j*32];
                v4[j] = v; s += v; qs += v*v;
            }
            #pragma unroll
            for (int off = 16; off; off >>= 1) {
                s  += __shfl_xor_sync(0xffffffff, s, off);
                qs += __shfl_xor_sync(0xffffffff, qs, off);
            }
            float mu = s * (1.0f/128.0f);
            float rs = rsqrtf(qs * (1.0f/128.0f) - mu*mu + 1e-5f);
            long grow = m0 + row;
            #pragma unroll
            for (int j = 0; j < 4; j++) {
                int e = l + j*32;
                float v = (v4[j] - mu) * rs * aux[e] + aux2[e];
                __half hi, lo;
                split_h(v, hi, lo);
                outh[grow*256 + e]       = hi;
                outh[grow*256 + 128 + e] = lo;
            }
        }
        return;
    }

    #pragma unroll
    for (int mt = 0; mt < 2; mt++) {
        int r0 = m0 + m_off + mt*16 + (l >> 2);
        #pragma unroll
        for (int n8 = 0; n8 < 4; n8++) {
            int cc = n0 + n_off + n8*8 + (l & 3)*2;
            float d0 = acc[mt][n8][0], d1 = acc[mt][n8][1];
            float d2 = acc[mt][n8][2], d3 = acc[mt][n8][3];
            if (EPI == 2) {
                float v0 = d0 + aux[(long)r0*128 + cc];
                float v1 = d1 + aux[(long)r0*128 + cc + 1];
                float v2 = d2 + aux[(long)(r0+8)*128 + cc];
                float v3 = d3 + aux[(long)(r0+8)*128 + cc + 1];
                outh[(long)r0*128 + cc]         = __float2half(v0);
                outh[(long)r0*128 + cc + 1]     = __float2half(v1);
                outh[(long)(r0+8)*128 + cc]     = __float2half(v2);
                outh[(long)(r0+8)*128 + cc + 1] = __float2half(v3);
            } else if (EPI == 6) {
                __half* q0 = outh + (long)r0*ldo + cc;
                __half* q1 = outh + (long)(r0+8)*ldo + cc;
                q0[0] = __float2half(d0); q0[1] = __float2half(d1);
                q1[0] = __float2half(d2); q1[1] = __float2half(d3);
            } else {
                float* p0 = Out + ((long)z*o_zstride + r0    )*ldo + cc;
                float* p1 = Out + ((long)z*o_zstride + r0 + 8)*ldo + cc;
                if (EPI == 1) { d0 += p0[0]; d1 += p0[1]; d2 += p1[0]; d3 += p1[1]; }
                p0[0] = d0; p0[1] = d1;
                p1[0] = d2; p1[1] = d3;
            }
        }
    }
}

// -------------------- conv_h: single-wave 128x256 tiles, 512 thr, 3 stages --------------------
#define H2_A (128*ROWB)
#define H2_B (256*ROWB)
#define H2_STAGE (H2_A + H2_B)
#define H2_SMEM (3*H2_STAGE)       // 165888

__global__ __launch_bounds__(512, 1)
void convh2_mma(const __half* __restrict__ A, const __half* __restrict__ Bw,
                float* __restrict__ Out) {
    extern __shared__ char smem[];
    uint32_t sb = smem_u32(smem);
    int tid = threadIdx.x;
    int m0 = blockIdx.x * 128;
    int n0 = blockIdx.y * 256;

    auto load_chunk = [&](int c, int st) {
        int tap  = c >> 1;
        int koff = (c & 1) * 64;
        int ky = tap/3 - 1, kx = tap%3 - 1;
        uint32_t a_st = sb + st*H2_STAGE;
        uint32_t b_st = a_st + H2_A;
        #pragma unroll
        for (int i = 0; i < 2; i++) {
            int id = tid + i*512;
            int row = id >> 3, seg = id & 7;
            int p = m0 + row;
            int y = (p >> 5) & 31, x = p & 31;
            int yy = y + ky, xx = x + kx;
            bool v = ((unsigned)yy < 32u) && ((unsigned)xx < 32u);
            const __half* asrc = v
                ? (A + ((long)(p >> 10)*1024 + (yy<<5) + xx)*128 + koff + seg*8)
                : A;
            cp16(a_st + row*ROWB + seg*16, asrc, v);
        }
        #pragma unroll
        for (int i = 0; i < 4; i++) {
            int id = tid + i*512;
            int row = id >> 3, seg = id & 7;
            const __half* bsrc = Bw + (long)(n0 + row)*1152 + c*64 + seg*8;
            cp16(b_st + row*ROWB + seg*16, bsrc, true);
        }
        CP_COMMIT();
    };

    int w = tid >> 5, l = tid & 31;
    int m_off = (w >> 2) * 32;
    int n_off = (w & 3) * 64;
    int lr = l & 15, lh = (l >> 4) << 4;

    float acc[2][8][4];
    #pragma unroll
    for (int i=0;i<2;i++)
        #pragma unroll
        for (int j=0;j<8;j++)
            #pragma unroll
            for (int q=0;q<4;q++) acc[i][j][q]=0.f;

    load_chunk(0, 0);
    load_chunk(1, 1);

    for (int c = 0; c < 18; c++) {
        int st = c % 3;
        if (c + 2 < 18) load_chunk(c + 2, (c + 2) % 3);
        else CP_COMMIT();
        CP_WAIT2();
        __syncthreads();

        uint32_t a_st = sb + st*H2_STAGE;
        uint32_t b_st = a_st + H2_A;
        #pragma unroll
        for (int ks = 0; ks < 4; ks++) {
            uint32_t af[2][4], bf[4][4];
            #pragma unroll
            for (int mt = 0; mt < 2; mt++)
                ldm_x4(af[mt], a_st + (m_off + mt*16 + lr)*ROWB + ks*32 + lh);
            #pragma unroll
            for (int nt = 0; nt < 4; nt++)
                ldm_x4(bf[nt], b_st + (n_off + nt*16 + lr)*ROWB + ks*32 + lh);
            #pragma unroll
            for (int mt = 0; mt < 2; mt++) {
                #pragma unroll
                for (int n8 = 0; n8 < 8; n8++) {
                    int nt = n8 >> 1, hi = n8 & 1;
                    mma16816(acc[mt][n8], af[mt], bf[nt][hi], bf[nt][2+hi]);
                }
            }
        }
        __syncthreads();
    }

    #pragma unroll
    for (int mt = 0; mt < 2; mt++) {
        int r0 = m0 + m_off + mt*16 + (l >> 2);
        #pragma unroll
        for (int n8 = 0; n8 < 8; n8++) {
            int cc = n0 + n_off + n8*8 + (l & 3)*2;
            float* p0 = Out + (long)r0*OC + cc;
            float* p1 = Out + (long)(r0+8)*OC + cc;
            p0[0] += acc[mt][n8][0]; p0[1] += acc[mt][n8][1];
            p1[0] += acc[mt][n8][2]; p1[1] += acc[mt][n8][3];
        }
    }
}

// -------------------- LSTM gates (float4 vectorized) --------------------
__global__ void gates_kernel(const float* __restrict__ cc,
                             float* __restrict__ cbuf,
                             __half* __restrict__ hp,
                             float* __restrict__ out, int s, int czero) {
    int idx = blockIdx.x*blockDim.x + threadIdx.x;
    if (idx >= Pn*32) return;
    int p = idx >> 5, e4 = idx & 31;
    const float4* row = (const float4*)(cc + (long)p*OC);
    float4 ci = row[e4];
    float4 cf = row[32 + e4];
    float4 co = row[64 + e4];
    float4 cg = row[96 + e4];
    float4* crow = (float4*)(cbuf + (long)p*128);
    float4 cp = czero ? make_float4(0.f,0.f,0.f,0.f) : crow[e4];
    float cn0 = (1.f/(1.f+__expf(-cf.x)))*cp.x + (1.f/(1.f+__expf(-ci.x)))*tanhf(cg.x);
    float cn1 = (1.f/(1.f+__expf(-cf.y)))*cp.y + (1.f/(1.f+__expf(-ci.y)))*tanhf(cg.y);
    float cn2 = (1.f/(1.f+__expf(-cf.z)))*cp.z + (1.f/(1.f+__expf(-ci.z)))*tanhf(cg.z);
    float cn3 = (1.f/(1.f+__expf(-cf.w)))*cp.w + (1.f/(1.f+__expf(-ci.w)))*tanhf(cg.w);
    float h0 = (1.f/(1.f+__expf(-co.x)))*tanhf(cn0);
    float h1 = (1.f/(1.f+__expf(-co.y)))*tanhf(cn1);
    float h2 = (1.f/(1.f+__expf(-co.z)))*tanhf(cn2);
    float h3 = (1.f/(1.f+__expf(-co.w)))*tanhf(cn3);
    crow[e4] = make_float4(cn0, cn1, cn2, cn3);
    __half2 ha = __halves2half2(__float2half(h0), __float2half(h1));
    __half2 hb = __halves2half2(__float2half(h2), __float2half(h3));
    float2 hpk;
    hpk.x = __uint_as_float(*(uint32_t*)&ha);
    hpk.y = __uint_as_float(*(uint32_t*)&hb);
    ((float2*)(hp + (long)p*128))[e4] = hpk;
    int b = p >> 10, pix = p & 1023;
    ((float4*)(out + ((long)(b*16+s)*1024 + pix)*128))[e4] = make_float4(h0, h1, h2, h3);
}

// -------------------- launch --------------------
extern "C" void kernel_launch(void* const* d_in, const int* in_sizes, int n_in,
                              void* d_out, int out_size) {
    const float* inputs  = (const float*)d_in[0];
    const float* W_proj  = (const float*)d_in[1];
    const float* ln_g    = (const float*)d_in[2];
    const float* ln_b    = (const float*)d_in[3];
    const float* W_in    = (const float*)d_in[4];
    const float* W_out   = (const float*)d_in[5];
    const float* conv_k  = (const float*)d_in[6];
    float* out = (float*)d_out;

    float *ccx, *cb;
    __half *qkvh, *xin2, *xs2, *ao, *xp, *hp, *bx, *bh, *bproj, *bqkv, *bout;
    cudaGetSymbolAddress((void**)&ccx, g_ccx);
    cudaGetSymbolAddress((void**)&cb,  g_c);
    cudaGetSymbolAddress((void**)&qkvh, g_qkvh);
    cudaGetSymbolAddress((void**)&xin2, g_xin2);
    cudaGetSymbolAddress((void**)&xs2, g_xs2);
    cudaGetSymbolAddress((void**)&ao,  g_ao);
    cudaGetSymbolAddress((void**)&xp,  g_xp);
    cudaGetSymbolAddress((void**)&hp,  g_hp);
    cudaGetSymbolAddress((void**)&bx,  g_bx);
    cudaGetSymbolAddress((void**)&bh,  g_bh);
    cudaGetSymbolAddress((void**)&bproj, g_bproj);
    cudaGetSymbolAddress((void**)&bqkv, g_bqkv);
    cudaGetSymbolAddress((void**)&bout, g_bout);

    cudaFuncSetAttribute((void*)gemm_mma<1,256,4,5>, cudaFuncAttributeMaxDynamicSharedMemorySize, GEMM_SMEM);
    cudaFuncSetAttribute((void*)gemm_mma<1,256,2,6>, cudaFuncAttributeMaxDynamicSharedMemorySize, GEMM_SMEM);
    cudaFuncSetAttribute((void*)gemm_mma<1,128,2,2>, cudaFuncAttributeMaxDynamicSharedMemorySize, GEMM_SMEM);
    cudaFuncSetAttribute((void*)gemm_mma<9,128,18,0>, cudaFuncAttributeMaxDynamicSharedMemorySize, GEMM_SMEM);
    cudaFuncSetAttribute((void*)convh2_mma, cudaFuncAttributeMaxDynamicSharedMemorySize, H2_SMEM);

    // plain side stream + events (same topology as the R14 run that passed
    // the teardown memory check with delta=0)
    cudaStream_t sA;
    cudaStreamCreate(&sA);
    cudaEvent_t evFork, evX[Sn];
    cudaEventCreateWithFlags(&evFork, cudaEventDisableTiming);
    for (int s = 0; s < Sn; s++)
        cudaEventCreateWithFlags(&evX[s], cudaEventDisableTiming);

    // conv weight reorder overlaps dense section on side stream
    reorder_conv<<<(int)(((long)OC*1152 + 255)/256), 256, 0, sA>>>(conv_k, bx, bh);

    reorder_dense<<<(640*128+255)/256, 256>>>(W_proj, W_in, W_out, bproj, bqkv, bout);
    split_in<<<(int)(((long)TOK*64+255)/256), 256>>>(inputs, xin2);

    // proj + silu + LN fused (2-term), writes xs2 [hi|lo]
    gemm_mma<1,256,4,5><<<dim3(TOK/128, 1, 1), 512, GEMM_SMEM>>>(
        xin2, bproj, nullptr, 0, ln_g, ln_b, xs2, 1024L, 0L, 0L);

    // qkv = xln @ W_in (2-term in, fp16 out)
    gemm_mma<1,256,2,6><<<dim3(TOK/128, 3, 1), 512, GEMM_SMEM>>>(
        xs2, bqkv, nullptr, 384, nullptr, nullptr, qkvh, 1024L, 0L, 0L);

    attn_core<<<Pn/2, 256>>>(qkvh, ao);

    // xres = ao @ W_out + inputs -> 1-term fp16 xp
    gemm_mma<1,128,2,2><<<dim3(TOK/128, 1, 1), 512, GEMM_SMEM>>>(
        ao, bout, nullptr, 0, inputs, nullptr, xp, 1024L, 0L, 0L);

    // ---- fork: conv_x per-step slices on side stream (after xp ready) ----
    cudaEventRecord(evFork, 0);
    cudaStreamWaitEvent(sA, evFork, 0);
    for (int z = 0; z < Sn; z++) {
        gemm_mma<9,128,18,0><<<dim3(Pn/128, 4, 1), 512, GEMM_SMEM, sA>>>(
            xp + (long)z*1024*128, bx, ccx + (long)z*Pn*OC, OC,
            nullptr, nullptr, nullptr, 16384L, 0L, 0L);
        cudaEventRecord(evX[z], sA);
    }

    // ---- main stream: sequential ConvLSTM chain ----
    for (int s = 0; s < Sn; s++) {
        cudaStreamWaitEvent(0, evX[s], 0);
        if (s > 0) {
            convh2_mma<<<dim3(Pn/128, 2, 1), 512, H2_SMEM>>>(
                hp, bh, ccx + (long)s*Pn*OC);
        }
        gates_kernel<<<(Pn*32+255)/256, 256>>>(ccx + (long)s*Pn*OC, cb, hp, out, s, s == 0);
    }
}